// round 12
// baseline (speedup 1.0000x reference)
#include <cuda_runtime.h>
#include <cuda_bf16.h>
#include <cuda_fp16.h>
#include <math.h>
#include <stdint.h>

// ---------------- problem constants ----------------
#define B_    2
#define NIN   4096
#define NOUT  484
#define D_    384
#define H_    12
#define HD_   32
#define QG    22
#define GW_   64
#define MOUT  (B_*NOUT)   // 968
#define MIN_  (B_*NIN)    // 8192
#define BH_   (B_*H_)     // 24
#define NROT_ 16
#define LNEPS 1e-5f
#define EPSV  1.1920929e-07f
#define CKK   (49*D_)     // 18816 conv k-extent

#define XOUT_SZ  (MOUT*D_)                       // 371712
#define ATTN_SZ  ((size_t)BH_*NOUT*NIN)          // 47579136

// ---------------- scratch (device globals; no alloc allowed) ----------------
__device__ __nv_bfloat16 g_cwh[D_*CKK],  g_cwl[D_*CKK];       // conv w: [co][khw*384+ci]
__device__ __nv_bfloat16 g_kvwh[2*D_*D_], g_kvwl[2*D_*D_];
__device__ __nv_bfloat16 g_qwh[D_*D_],    g_qwl[D_*D_];
__device__ __nv_bfloat16 g_w1h[4*D_*D_],  g_w1l[4*D_*D_];
__device__ __nv_bfloat16 g_w2h[D_*4*D_],  g_w2l[D_*4*D_];
__device__ __nv_bfloat16 g_xh[MIN_*D_],   g_xl[MIN_*D_];       // pre-split input x
__device__ __nv_bfloat16 g_kh[BH_*NIN*HD_],  g_kl[BH_*NIN*HD_];
__device__ __nv_bfloat16 g_vth[BH_*HD_*NIN], g_vtl[BH_*HD_*NIN];  // [bh][d][n]
__device__ __half g_vph[BH_*HD_*NIN], g_vpl[BH_*HD_*NIN];         // colinv ⊙ V, fp16 hi/lo
__device__ __nv_bfloat16 g_qh[BH_*NOUT*HD_], g_ql[BH_*NOUT*HD_];
__device__ float g_xo[MOUT*D_];
__device__ float g_xout[MOUT*D_];                 // fallback only
__device__ float g_kv[MIN_*2*D_];
__device__ float g_qlin[MOUT*D_];
__device__ float g_attn[(size_t)BH_*NOUT*NIN];    // fp16 (E-1) store + fallback region
__device__ float g_rowsum[BH_*NOUT];
__device__ float g_colinv[BH_*NIN];
__device__ float g_S[BH_*4*HD_];                  // ones-row term per (bh, ksplit, d)
__device__ float g_h1[MOUT*4*D_];

// ---------------- helpers ----------------
__device__ __forceinline__ float gelu_f(float x){
    return 0.5f * x * (1.0f + erff(x * 0.70710678118654752f));
}
__device__ __forceinline__ void split1(float v, __nv_bfloat16& h, __nv_bfloat16& l){
    h = __float2bfloat16(v);
    l = __float2bfloat16(v - __bfloat162float(h));
}
__device__ __forceinline__ void split4(float4 v, unsigned& h0, unsigned& h1,
                                       unsigned& l0, unsigned& l1){
    __nv_bfloat162 hx = __floats2bfloat162_rn(v.x, v.y);
    __nv_bfloat162 hz = __floats2bfloat162_rn(v.z, v.w);
    float2 fx = __bfloat1622float2(hx);
    float2 fz = __bfloat1622float2(hz);
    __nv_bfloat162 lx = __floats2bfloat162_rn(v.x - fx.x, v.y - fx.y);
    __nv_bfloat162 lz = __floats2bfloat162_rn(v.z - fz.x, v.w - fz.y);
    h0 = *(unsigned*)&hx; h1 = *(unsigned*)&hz;
    l0 = *(unsigned*)&lx; l1 = *(unsigned*)&lz;
}
// FFMA-only exp (no MUFU), rel err ~1.2e-7
__device__ __forceinline__ float exp_fast(float x){
    float t = x * 1.4426950408889634f;
    float r = t + 12582912.0f;
    int   n = __float_as_int(r) - 0x4B400000;
    float f = t - (r - 12582912.0f);
    float p =            1.5403530e-4f;
    p = fmaf(p, f, 1.3333558e-3f);
    p = fmaf(p, f, 9.6181291e-3f);
    p = fmaf(p, f, 5.5504109e-2f);
    p = fmaf(p, f, 2.4022651e-1f);
    p = fmaf(p, f, 6.9314718e-1f);
    p = fmaf(p, f, 1.0f);
    return __int_as_float(__float_as_int(p) + (n << 23));
}
__device__ __forceinline__ void mma16816(float* c, const unsigned* a, const unsigned* b){
    asm volatile("mma.sync.aligned.m16n8k16.row.col.f32.bf16.bf16.f32 "
        "{%0,%1,%2,%3},{%4,%5,%6,%7},{%8,%9},{%0,%1,%2,%3};"
        : "+f"(c[0]), "+f"(c[1]), "+f"(c[2]), "+f"(c[3])
        : "r"(a[0]), "r"(a[1]), "r"(a[2]), "r"(a[3]), "r"(b[0]), "r"(b[1]));
}
__device__ __forceinline__ void mma16816h(float* c, const unsigned* a, const unsigned* b){
    asm volatile("mma.sync.aligned.m16n8k16.row.col.f32.f16.f16.f32 "
        "{%0,%1,%2,%3},{%4,%5,%6,%7},{%8,%9},{%0,%1,%2,%3};"
        : "+f"(c[0]), "+f"(c[1]), "+f"(c[2]), "+f"(c[3])
        : "r"(a[0]), "r"(a[1]), "r"(a[2]), "r"(a[3]), "r"(b[0]), "r"(b[1]));
}

// ---------------- prologue pack kernels ----------------
__global__ void packT_kernel(const float* __restrict__ src, __nv_bfloat16* __restrict__ h,
                             __nv_bfloat16* __restrict__ l, int K, int N){
    int idx = blockIdx.x*blockDim.x + threadIdx.x;
    if (idx >= K*N) return;
    int n = idx / K, k = idx % K;
    __nv_bfloat16 hh, ll; split1(src[(size_t)k*N + n], hh, ll);
    h[idx] = hh; l[idx] = ll;
}
__global__ void packconvT_kernel(const float* __restrict__ w, __nv_bfloat16* __restrict__ h,
                                 __nv_bfloat16* __restrict__ l){
    int idx = blockIdx.x*blockDim.x + threadIdx.x;
    if (idx >= D_*CKK) return;
    int co = idx / CKK, r = idx % CKK;
    int khw = r / D_, ci = r % D_;
    __nv_bfloat16 hh, ll; split1(w[((size_t)co*D_ + ci)*49 + khw], hh, ll);
    h[idx] = hh; l[idx] = ll;
}
__global__ void splitf_kernel(const float* __restrict__ src, __nv_bfloat16* __restrict__ h,
                              __nv_bfloat16* __restrict__ l, int n){
    int i = blockIdx.x*blockDim.x + threadIdx.x;
    if (i >= n) return;
    __nv_bfloat16 hh, ll; split1(src[i], hh, ll);
    h[i] = hh; l[i] = ll;
}
__global__ void seed_kernel(const float* __restrict__ b, float* __restrict__ o, int M, int N){
    int idx = blockIdx.x*blockDim.x + threadIdx.x;
    if (idx < M*N) o[idx] = b[idx % N];
}
// per-iter prep: xo=0, qlin=q_b, rowsum=0
__global__ void prep_kernel(const float* __restrict__ qb, float* __restrict__ qlin,
                            float* __restrict__ xo, float* __restrict__ rowsum){
    int i = blockIdx.x*blockDim.x + threadIdx.x;
    if (i < MOUT*D_){ xo[i] = 0.f; qlin[i] = qb[i % D_]; }
    if (i < BH_*NOUT) rowsum[i] = 0.f;
}

// ---------------- rose (rotary) producing bf16 hi/lo directly ----------------
__global__ void rose_hl_kernel(const float* __restrict__ src, int stride, int off,
                               __nv_bfloat16* __restrict__ dh, __nv_bfloat16* __restrict__ dl,
                               int N, int Gw, float sp0, float sp1,
                               const float* __restrict__ fr, const float* __restrict__ temp,
                               int applyTemp){
    int idx = blockIdx.x*blockDim.x + threadIdx.x;
    int total = BH_ * N * HD_;
    if (idx >= total) return;
    int hd = idx & 31;
    int n  = (idx >> 5) % N;
    int bh = idx / (N*32);
    int h = bh % H_, b = bh / H_;
    const float* sp = src + ((size_t)b*N + n)*stride + off + h*HD_;
    float val;
    if (hd < NROT_){
        int m = hd >> 1, s = m >> 2, p = m & 3;
        float coord = (s == 0) ? (float)(n / Gw) * sp0 : (float)(n % Gw) * sp1;
        float ang = coord * fr[(h*2 + s)*4 + p];
        float cs, sn; sincosf(ang, &sn, &cs);
        float x1 = sp[2*m], x2 = sp[2*m+1];
        val = (hd & 1) ? (x1*sn + x2*cs) : (x1*cs - x2*sn);
    } else {
        val = sp[hd];
    }
    if (applyTemp) val *= temp[0];
    __nv_bfloat16 hh, ll; split1(val, hh, ll);
    dh[idx] = hh; dl[idx] = ll;
}
__global__ void vT_hl_kernel(const float* __restrict__ kv, __nv_bfloat16* __restrict__ th,
                             __nv_bfloat16* __restrict__ tl){
    int i = blockIdx.x*blockDim.x + threadIdx.x;
    if (i >= BH_*HD_*NIN) return;
    int n  = i % NIN;
    int d  = (i / NIN) % HD_;
    int bh = i / (NIN*HD_);
    int h = bh % H_, b = bh / H_;
    float v = kv[((size_t)b*NIN + n)*(2*D_) + D_ + h*HD_ + d];
    __nv_bfloat16 hh, ll; split1(v, hh, ll);
    th[i] = hh; tl[i] = ll;
}

// ================= HMMA bf16-split dense GEMM =================
#define ASTR 40

struct Frag { unsigned ah[2][4], al[2][4], bh[4][2], bl[4][2]; };

__device__ __forceinline__ void load_frags(Frag& f, const __nv_bfloat16* Ah, const __nv_bfloat16* Al,
                                           const __nv_bfloat16* Bh, const __nv_bfloat16* Bl,
                                           int wm, int wn, int ks, int g, int c2){
    #pragma unroll
    for (int t = 0; t < 2; t++){
        int rb = (wm*32 + t*16 + g)*ASTR + ks + c2;
        f.ah[t][0] = *(const unsigned*)(Ah + rb);
        f.ah[t][1] = *(const unsigned*)(Ah + rb + 8*ASTR);
        f.ah[t][2] = *(const unsigned*)(Ah + rb + 8);
        f.ah[t][3] = *(const unsigned*)(Ah + rb + 8*ASTR + 8);
        f.al[t][0] = *(const unsigned*)(Al + rb);
        f.al[t][1] = *(const unsigned*)(Al + rb + 8*ASTR);
        f.al[t][2] = *(const unsigned*)(Al + rb + 8);
        f.al[t][3] = *(const unsigned*)(Al + rb + 8*ASTR + 8);
    }
    #pragma unroll
    for (int u = 0; u < 4; u++){
        int nb = (wn*32 + u*8 + g)*ASTR + ks + c2;
        f.bh[u][0] = *(const unsigned*)(Bh + nb);
        f.bh[u][1] = *(const unsigned*)(Bh + nb + 8);
        f.bl[u][0] = *(const unsigned*)(Bl + nb);
        f.bl[u][1] = *(const unsigned*)(Bl + nb + 8);
    }
}
__device__ __forceinline__ void do_mmas(float (*acc)[4], const Frag& f){
    #pragma unroll
    for (int t = 0; t < 2; t++)
        #pragma unroll
        for (int u = 0; u < 4; u++){
            mma16816(acc[t*4+u], f.ah[t], f.bh[u]);
            mma16816(acc[t*4+u], f.ah[t], f.bl[u]);
            mma16816(acc[t*4+u], f.al[t], f.bh[u]);
        }
}
__device__ __forceinline__ void epi(float (*acc)[4], const float* __restrict__ bias,
                                    float* __restrict__ C, int M, int N, int m0, int n0,
                                    int wm, int wn, int g, int c2, int act, int atom){
    #pragma unroll
    for (int t = 0; t < 2; t++){
        int r0 = m0 + wm*32 + t*16 + g;
        #pragma unroll
        for (int u = 0; u < 4; u++){
            int cb = n0 + wn*32 + u*8 + c2;
            float* ac = acc[t*4+u];
            if (atom){
                if (r0 < M){
                    atomicAdd(&C[(size_t)r0*N + cb],     ac[0]);
                    atomicAdd(&C[(size_t)r0*N + cb + 1], ac[1]);
                }
                if (r0 + 8 < M){
                    atomicAdd(&C[(size_t)(r0+8)*N + cb],     ac[2]);
                    atomicAdd(&C[(size_t)(r0+8)*N + cb + 1], ac[3]);
                }
            } else {
                float b0 = bias[cb], b1 = bias[cb+1];
                float o0 = ac[0]+b0, o1 = ac[1]+b1, o2 = ac[2]+b0, o3 = ac[3]+b1;
                if (act){ o0=gelu_f(o0); o1=gelu_f(o1); o2=gelu_f(o2); o3=gelu_f(o3); }
                if (r0 < M){ C[(size_t)r0*N + cb] = o0; C[(size_t)r0*N + cb + 1] = o1; }
                if (r0 + 8 < M){ C[(size_t)(r0+8)*N + cb] = o2; C[(size_t)(r0+8)*N + cb + 1] = o3; }
            }
        }
    }
}
__device__ __forceinline__ void fillA(__nv_bfloat16* Ah, __nv_bfloat16* Al,
                                      const float* __restrict__ A, int M, int K,
                                      int m0, int k0, int tid){
    #pragma unroll
    for (int i = 0; i < 4; i++){
        int e = tid + i*256;
        int row = e >> 3, kg = (e & 7)*4;
        float4 v = (m0+row < M) ? *(const float4*)(A + (size_t)(m0+row)*K + k0 + kg)
                                : make_float4(0.f,0.f,0.f,0.f);
        unsigned h0,h1,l0,l1; split4(v, h0,h1,l0,l1);
        unsigned* ph = (unsigned*)&Ah[row*ASTR + kg];
        unsigned* pl = (unsigned*)&Al[row*ASTR + kg];
        ph[0]=h0; ph[1]=h1; pl[0]=l0; pl[1]=l1;
    }
}
__device__ __forceinline__ void fillB(__nv_bfloat16* Bh, __nv_bfloat16* Bl,
                                      const __nv_bfloat16* __restrict__ Wh,
                                      const __nv_bfloat16* __restrict__ Wl,
                                      size_t rowbase, int Kst, int n0, int tid){
    int n  = tid >> 2;
    int kb = (tid & 3)*8;
    const unsigned* ph = (const unsigned*)Wh + ((rowbase + (size_t)(n0+n)*Kst + kb) >> 1);
    const unsigned* pl = (const unsigned*)Wl + ((rowbase + (size_t)(n0+n)*Kst + kb) >> 1);
    unsigned* sh = (unsigned*)&Bh[n*ASTR + kb];
    unsigned* sl = (unsigned*)&Bl[n*ASTR + kb];
    #pragma unroll
    for (int j = 0; j < 4; j++){ sh[j] = ph[j]; sl[j] = pl[j]; }
}

__global__ __launch_bounds__(256, 2)
void mgemm_kernel(const float* __restrict__ A, const __nv_bfloat16* __restrict__ Wh,
                  const __nv_bfloat16* __restrict__ Wl,
                  const float* __restrict__ bias, float* __restrict__ C,
                  int M, int N, int K, int kSlice, int act, int atom){
    __shared__ __align__(16) __nv_bfloat16 Ah[128*ASTR], Al[128*ASTR];
    __shared__ __align__(16) __nv_bfloat16 Bh[64*ASTR],  Bl[64*ASTR];
    int tid = threadIdx.x, lane = tid & 31, wid = tid >> 5;
    int wm = wid >> 1, wn = wid & 1;
    int g = lane >> 2, c2 = (lane & 3)*2;
    int m0 = blockIdx.y*128, n0 = blockIdx.x*64;
    int kb0 = blockIdx.z*kSlice, kend = kb0 + kSlice;
    float acc[8][4] = {};
    for (int k0 = kb0; k0 < kend; k0 += 32){
        fillA(Ah, Al, A, M, K, m0, k0, tid);
        fillB(Bh, Bl, Wh, Wl, (size_t)k0, K, n0, tid);
        __syncthreads();
        #pragma unroll
        for (int ks = 0; ks < 32; ks += 16){
            Frag f;
            load_frags(f, Ah, Al, Bh, Bl, wm, wn, ks, g, c2);
            do_mmas(acc, f);
        }
        __syncthreads();
    }
    epi(acc, bias, C, M, N, m0, n0, wm, wn, g, c2, act, atom);
}

// A pre-split variant (for kv GEMM on x)
__global__ __launch_bounds__(256, 2)
void mgemm_pre_kernel(const __nv_bfloat16* __restrict__ Xh, const __nv_bfloat16* __restrict__ Xl,
                      const __nv_bfloat16* __restrict__ Wh, const __nv_bfloat16* __restrict__ Wl,
                      const float* __restrict__ bias, float* __restrict__ C,
                      int M, int N, int K){
    __shared__ __align__(16) __nv_bfloat16 Ah[128*ASTR], Al[128*ASTR];
    __shared__ __align__(16) __nv_bfloat16 Bh[64*ASTR],  Bl[64*ASTR];
    int tid = threadIdx.x, lane = tid & 31, wid = tid >> 5;
    int wm = wid >> 1, wn = wid & 1;
    int g = lane >> 2, c2 = (lane & 3)*2;
    int m0 = blockIdx.y*128, n0 = blockIdx.x*64;
    float acc[8][4] = {};
    for (int k0 = 0; k0 < K; k0 += 32){
        #pragma unroll
        for (int i = 0; i < 4; i++){
            int e = tid + i*256;
            int row = e >> 3, kg = (e & 7)*4;
            size_t off = (size_t)(m0+row)*K + k0 + kg;
            uint2 h = make_uint2(0u,0u), l = h;
            if (m0+row < M){
                h = *(const uint2*)(Xh + off);
                l = *(const uint2*)(Xl + off);
            }
            *(uint2*)&Ah[row*ASTR + kg] = h;
            *(uint2*)&Al[row*ASTR + kg] = l;
        }
        fillB(Bh, Bl, Wh, Wl, (size_t)k0, K, n0, tid);
        __syncthreads();
        #pragma unroll
        for (int ks = 0; ks < 32; ks += 16){
            Frag f;
            load_frags(f, Ah, Al, Bh, Bl, wm, wn, ks, g, c2);
            do_mmas(acc, f);
        }
        __syncthreads();
    }
    epi(acc, bias, C, M, N, m0, n0, wm, wn, g, c2, 0, 0);
}

// conv implicit GEMM with pre-split x; grid.z = 7 kh-slices, atomic epilogue (R10 form)
__global__ __launch_bounds__(256, 2)
void mconv_kernel(const __nv_bfloat16* __restrict__ Xh, const __nv_bfloat16* __restrict__ Xl,
                  const __nv_bfloat16* __restrict__ Wh, const __nv_bfloat16* __restrict__ Wl,
                  float* __restrict__ C){
    __shared__ __align__(16) __nv_bfloat16 Ah[128*ASTR], Al[128*ASTR];
    __shared__ __align__(16) __nv_bfloat16 Bh[64*ASTR],  Bl[64*ASTR];
    int tid = threadIdx.x, lane = tid & 31, wid = tid >> 5;
    int wm = wid >> 1, wn = wid & 1;
    int g = lane >> 2, c2 = (lane & 3)*2;
    int m0 = blockIdx.y*128, n0 = blockIdx.x*64;
    int slice = blockIdx.z;
    float acc[8][4] = {};
    for (int kc = 0; kc < 7*D_; kc += 32){
        int khw = slice*7 + kc/D_;
        int cib = kc % D_;
        int kh = khw/7, kw = khw%7;
        #pragma unroll
        for (int i = 0; i < 4; i++){
            int e = tid + i*256;
            int row = e >> 3, kg = (e & 7)*4;
            int m = m0 + row;
            uint2 h = make_uint2(0u,0u), l = h;
            if (m < MOUT){
                int bb = m / NOUT, rr = m % NOUT;
                int oh = rr / QG, ow = rr % QG;
                int ih = oh*3 - 3 + kh, iw = ow*3 - 3 + kw;
                if ((unsigned)ih < 64u && (unsigned)iw < 64u){
                    size_t off = ((size_t)(bb*NIN + ih*GW_ + iw))*D_ + cib + kg;
                    h = *(const uint2*)(Xh + off);
                    l = *(const uint2*)(Xl + off);
                }
            }
            *(uint2*)&Ah[row*ASTR + kg] = h;
            *(uint2*)&Al[row*ASTR + kg] = l;
        }
        fillB(Bh, Bl, Wh, Wl, (size_t)(khw*D_ + cib), CKK, n0, tid);
        __syncthreads();
        #pragma unroll
        for (int ks = 0; ks < 32; ks += 16){
            Frag f;
            load_frags(f, Ah, Al, Bh, Bl, wm, wn, ks, g, c2);
            do_mmas(acc, f);
        }
        __syncthreads();
    }
    epi(acc, (const float*)0, C, MOUT, D_, m0, n0, wm, wn, g, c2, 0, 1);
}

// ---------------- one-pass layernorm over D=384, optional residual-add -------------
__global__ void ln_kernel(const float* __restrict__ X, const float* __restrict__ g,
                          const float* __restrict__ bt, float* __restrict__ out, int add){
    int row = blockIdx.x, tid = threadIdx.x;
    float x = X[(size_t)row*D_ + tid];
    __shared__ float w1s[12], w2s[12];
    float s1 = x, s2 = x*x;
    #pragma unroll
    for (int o = 16; o > 0; o >>= 1){
        s1 += __shfl_down_sync(0xffffffffu, s1, o);
        s2 += __shfl_down_sync(0xffffffffu, s2, o);
    }
    if ((tid & 31) == 0){ w1s[tid >> 5] = s1; w2s[tid >> 5] = s2; }
    __syncthreads();
    if (tid == 0){
        float t1 = 0.f, t2 = 0.f;
        #pragma unroll
        for (int i = 0; i < 12; i++){ t1 += w1s[i]; t2 += w2s[i]; }
        w1s[0] = t1; w2s[0] = t2;
    }
    __syncthreads();
    float mu  = w1s[0] * (1.0f/D_);
    float var = w2s[0] * (1.0f/D_) - mu*mu;
    float y = (x - mu) * rsqrtf(var + LNEPS) * g[tid] + bt[tid];
    size_t o_ = (size_t)row*D_ + tid;
    out[o_] = add ? (out[o_] + y) : y;
}

// ======== HMMA scores: E = exp(Q K^T); store d = E-1 as fp16; fused row-sum ========
__global__ __launch_bounds__(256)
void mscore_kernel(const __nv_bfloat16* __restrict__ Qh, const __nv_bfloat16* __restrict__ Ql,
                   const __nv_bfloat16* __restrict__ Kh, const __nv_bfloat16* __restrict__ Kl,
                   __half* __restrict__ Eh, float* __restrict__ rowsum){
    __shared__ __align__(16) __nv_bfloat16 Qhs[64*ASTR], Qls[64*ASTR];
    __shared__ __align__(16) __nv_bfloat16 Khs[128*ASTR], Kls[128*ASTR];
    __shared__ float rs[64];
    int tid = threadIdx.x, lane = tid & 31, wid = tid >> 5;
    int wq = wid >> 2, wk = wid & 3;
    int g = lane >> 2, c2 = (lane & 3)*2;
    int kt = blockIdx.x*128, q0 = blockIdx.y*64, bh = blockIdx.z;
    if (tid < 64) rs[tid] = 0.f;
    {
        int row = tid >> 2, kb = (tid & 3)*8;
        unsigned* sh = (unsigned*)&Qhs[row*ASTR + kb];
        unsigned* sl = (unsigned*)&Qls[row*ASTR + kb];
        if (q0 + row < NOUT){
            size_t e32 = ((size_t)(bh*NOUT + q0 + row)*HD_ + kb) >> 1;
            const unsigned* ph = (const unsigned*)Qh + e32;
            const unsigned* pl = (const unsigned*)Ql + e32;
            #pragma unroll
            for (int j = 0; j < 4; j++){ sh[j] = ph[j]; sl[j] = pl[j]; }
        } else {
            #pragma unroll
            for (int j = 0; j < 4; j++){ sh[j] = 0u; sl[j] = 0u; }
        }
    }
    {
        int row = tid >> 1, kb = (tid & 1)*16;
        size_t e32 = ((size_t)(bh*NIN + kt + row)*HD_ + kb) >> 1;
        const unsigned* ph = (const unsigned*)Kh + e32;
        const unsigned* pl = (const unsigned*)Kl + e32;
        unsigned* sh = (unsigned*)&Khs[row*ASTR + kb];
        unsigned* sl = (unsigned*)&Kls[row*ASTR + kb];
        #pragma unroll
        for (int j = 0; j < 8; j++){ sh[j] = ph[j]; sl[j] = pl[j]; }
    }
    __syncthreads();
    float acc[2][4][4] = {};
    #pragma unroll
    for (int ks = 0; ks < 32; ks += 16){
        unsigned ah[2][4], al[2][4], bhf[4][2], blf[4][2];
        #pragma unroll
        for (int t = 0; t < 2; t++){
            int rb = (wq*32 + t*16 + g)*ASTR + ks + c2;
            ah[t][0] = *(const unsigned*)(Qhs + rb);
            ah[t][1] = *(const unsigned*)(Qhs + rb + 8*ASTR);
            ah[t][2] = *(const unsigned*)(Qhs + rb + 8);
            ah[t][3] = *(const unsigned*)(Qhs + rb + 8*ASTR + 8);
            al[t][0] = *(const unsigned*)(Qls + rb);
            al[t][1] = *(const unsigned*)(Qls + rb + 8*ASTR);
            al[t][2] = *(const unsigned*)(Qls + rb + 8);
            al[t][3] = *(const unsigned*)(Qls + rb + 8*ASTR + 8);
        }
        #pragma unroll
        for (int u = 0; u < 4; u++){
            int nb = (wk*32 + u*8 + g)*ASTR + ks + c2;
            bhf[u][0] = *(const unsigned*)(Khs + nb);
            bhf[u][1] = *(const unsigned*)(Khs + nb + 8);
            blf[u][0] = *(const unsigned*)(Kls + nb);
            blf[u][1] = *(const unsigned*)(Kls + nb + 8);
        }
        #pragma unroll
        for (int t = 0; t < 2; t++)
            #pragma unroll
            for (int u = 0; u < 4; u++){
                mma16816(acc[t][u], ah[t], bhf[u]);
                mma16816(acc[t][u], ah[t], blf[u]);
                mma16816(acc[t][u], al[t], bhf[u]);
            }
    }
    #pragma unroll
    for (int t = 0; t < 2; t++){
        int lr = wq*32 + t*16 + g;
        int r  = q0 + lr;
        float s0 = 0.f, s1 = 0.f;
        #pragma unroll
        for (int u = 0; u < 4; u++){
            int col = kt + wk*32 + u*8 + c2;
            float e0 = exp_fast(acc[t][u][0]), e1 = exp_fast(acc[t][u][1]);
            float e2 = exp_fast(acc[t][u][2]), e3 = exp_fast(acc[t][u][3]);
            __half2 v0 = __floats2half2_rn(e0 - 1.0f, e1 - 1.0f);
            __half2 v1 = __floats2half2_rn(e2 - 1.0f, e3 - 1.0f);
            if (r < NOUT)
                *(__half2*)(Eh + (size_t)(bh*NOUT + r)*NIN + col) = v0;
            if (r + 8 < NOUT)
                *(__half2*)(Eh + (size_t)(bh*NOUT + r + 8)*NIN + col) = v1;
            s0 += e0 + e1; s1 += e2 + e3;
        }
        s0 += __shfl_xor_sync(0xffffffffu, s0, 1);
        s0 += __shfl_xor_sync(0xffffffffu, s0, 2);
        s1 += __shfl_xor_sync(0xffffffffu, s1, 1);
        s1 += __shfl_xor_sync(0xffffffffu, s1, 2);
        if ((lane & 3) == 0){
            atomicAdd(&rs[lr], s0);
            atomicAdd(&rs[lr + 8], s1);
        }
    }
    __syncthreads();
    if (tid < 64 && q0 + tid < NOUT)
        atomicAdd(rowsum + bh*NOUT + q0 + tid, rs[tid]);
}

__global__ void rowinv_kernel(float* __restrict__ rowsum){
    int i = blockIdx.x*blockDim.x + threadIdx.x;
    if (i < BH_*NOUT) rowsum[i] = 1.f / rowsum[i];
}

__global__ void colsum_kernel(const __half* __restrict__ Eh, const float* __restrict__ rinv,
                              float* __restrict__ colinv){
    int bh = blockIdx.y;
    int col = blockIdx.x*256 + threadIdx.x;
    const __half* a = Eh + (size_t)bh*NOUT*NIN + col;
    const float* ri = rinv + bh*NOUT;
    float s = 0.f;
    #pragma unroll 4
    for (int qi = 0; qi < NOUT; qi++)
        s += (1.0f + __half2float(a[(size_t)qi*NIN])) * __ldg(ri + qi);
    colinv[bh*NIN + col] = 1.f / (s + EPSV);
}

// vprep: V' = colinv ⊙ V as fp16 hi/lo, plus S[bh][ks][d] = sum_slice V'
// grid (BH_, HD_), 256 threads: thread t handles n = t*16 .. t*16+15
__global__ void vprep_kernel(const __nv_bfloat16* __restrict__ Vth,
                             const __nv_bfloat16* __restrict__ Vtl,
                             const float* __restrict__ colinv,
                             __half* __restrict__ Vph, __half* __restrict__ Vpl,
                             float* __restrict__ S){
    int bh = blockIdx.x, d = blockIdx.y;
    int t = threadIdx.x;
    size_t base = (size_t)(bh*HD_ + d)*NIN;
    const float* ci = colinv + bh*NIN;
    float s = 0.f;
    int n0 = t*16;
    #pragma unroll
    for (int j = 0; j < 16; j++){
        int n = n0 + j;
        float v = __bfloat162float(Vth[base + n]) + __bfloat162float(Vtl[base + n]);
        float a = v * ci[n];
        s += a;
        __half h = __float2half_rn(a);
        __half l = __float2half_rn(a - __half2float(h));
        Vph[base + n] = h;
        Vpl[base + n] = l;
    }
    // reduce within 64-thread groups (each group = one 1024-k split)
    __shared__ float red[256];
    red[t] = s;
    __syncthreads();
    if ((t & 63) == 0){
        float tot = 0.f;
        #pragma unroll
        for (int p = 0; p < 64; p++) tot += red[(t & 192) + p];
        S[(bh*4 + (t >> 6))*HD_ + d] = tot;
    }
}

// ======== HMMA PV: upd = rinv ⊙ (S + d @ V'), split-K=4, pure-copy fills ========
#define PSTR 72
__global__ __launch_bounds__(256)
void mpv_kernel(const __half* __restrict__ Eh,
                const float* __restrict__ rinv, const float* __restrict__ colinv,
                const __half* __restrict__ Vph, const __half* __restrict__ Vpl,
                const float* __restrict__ S,
                float* __restrict__ out, float* __restrict__ outk, float* __restrict__ outq,
                int writeout){
    __shared__ __align__(16) __half Ads[64*PSTR];
    __shared__ __align__(16) __half Vhs[32*PSTR], Vls[32*PSTR];
    int tid = threadIdx.x, lane = tid & 31, wid = tid >> 5;
    int wq = wid >> 1, wd = wid & 1;
    int g = lane >> 2, c2 = (lane & 3)*2;
    int q0 = blockIdx.x*64, bh = blockIdx.y;
    int ksplit = blockIdx.z;
    int ks0 = ksplit*1024;
    float acc[2][4] = {};
    int frow = tid >> 4, fcol = (tid & 15)*4;
    float rv[4];
    #pragma unroll
    for (int i = 0; i < 4; i++){
        int r = q0 + frow + i*16;
        rv[i] = (r < NOUT) ? rinv[bh*NOUT + r] : 0.f;
    }
    for (int c = 0; c < 16; c++){
        int k0 = ks0 + c*64;
        #pragma unroll
        for (int i = 0; i < 4; i++){
            int row = frow + i*16;
            int r = q0 + row;
            uint2 u = make_uint2(0u, 0u);
            size_t base = (size_t)(bh*NOUT + (r < NOUT ? r : 0))*NIN + k0 + fcol;
            if (r < NOUT) u = *(const uint2*)(Eh + base);
            *(uint2*)&Ads[row*PSTR + fcol] = u;
            if (writeout && r < NOUT){
                float2 f0 = __half22float2(*(__half2*)&u.x);
                float2 f1 = __half22float2(*(__half2*)&u.y);
                float4 cv = *(const float4*)(colinv + bh*NIN + k0 + fcol);
                float rvi = rv[i];
                float4 ak, aq;
                ak.x = (1.0f+f0.x)*rvi; ak.y = (1.0f+f0.y)*rvi;
                ak.z = (1.0f+f1.x)*rvi; ak.w = (1.0f+f1.y)*rvi;
                aq.x = ak.x*cv.x; aq.y = ak.y*cv.y; aq.z = ak.z*cv.z; aq.w = ak.w*cv.w;
                *(float4*)(outk + base) = ak;
                *(float4*)(outq + base) = aq;
            }
        }
        {
            int d = tid >> 3, kb = (tid & 7)*8;
            size_t e32 = ((size_t)(bh*HD_ + d)*NIN + k0 + kb) >> 1;
            const unsigned* ph = (const unsigned*)Vph + e32;
            const unsigned* pl = (const unsigned*)Vpl + e32;
            unsigned* sh = (unsigned*)&Vhs[d*PSTR + kb];
            unsigned* sl = (unsigned*)&Vls[d*PSTR + kb];
            #pragma unroll
            for (int j = 0; j < 4; j++){ sh[j] = ph[j]; sl[j] = pl[j]; }
        }
        __syncthreads();
        #pragma unroll
        for (int ks = 0; ks < 64; ks += 16){
            unsigned a_[4];
            int rb = (wq*16 + g)*PSTR + ks + c2;
            a_[0] = *(const unsigned*)(Ads + rb);
            a_[1] = *(const unsigned*)(Ads + rb + 8*PSTR);
            a_[2] = *(const unsigned*)(Ads + rb + 8);
            a_[3] = *(const unsigned*)(Ads + rb + 8*PSTR + 8);
            #pragma unroll
            for (int u = 0; u < 2; u++){
                unsigned b_h[2], b_l[2];
                int nb = (wd*16 + u*8 + g)*PSTR + ks + c2;
                b_h[0] = *(const unsigned*)(Vhs + nb);
                b_h[1] = *(const unsigned*)(Vhs + nb + 8);
                b_l[0] = *(const unsigned*)(Vls + nb);
                b_l[1] = *(const unsigned*)(Vls + nb + 8);
                mma16816h(acc[u], a_, b_h);
                mma16816h(acc[u], a_, b_l);
            }
        }
        __syncthreads();
    }
    int b = bh / H_, h = bh % H_;
    int r0 = q0 + wq*16 + g;
    float rv0 = (r0     < NOUT) ? rinv[bh*NOUT + r0]     : 0.f;
    float rv8 = (r0 + 8 < NOUT) ? rinv[bh*NOUT + r0 + 8] : 0.f;
    #pragma unroll
    for (int u = 0; u < 2; u++){
        int dcol = wd*16 + u*8 + c2;
        float S0 = S[(bh*4 + ksplit)*HD_ + dcol];
        float S1 = S[(bh*4 + ksplit)*HD_ + dcol + 1];
        int col = h*HD_ + dcol;
        if (r0 < NOUT){
            atomicAdd(out + (size_t)(b*NOUT + r0)*D_ + col,     rv0*(acc[u][0] + S0));
            atomicAdd(out + (size_t)(b*NOUT + r0)*D_ + col + 1, rv0*(acc[u][1] + S1));
        }
        if (r0 + 8 < NOUT){
            atomicAdd(out + (size_t)(b*NOUT + r0 + 8)*D_ + col,     rv8*(acc[u][2] + S0));
            atomicAdd(out + (size_t)(b*NOUT + r0 + 8)*D_ + col + 1, rv8*(acc[u][3] + S1));
        }
    }
}

// ---------------- host orchestration ----------------------------------------------
extern "C" void kernel_launch(void* const* d_in, const int* in_sizes, int n_in,
                              void* d_out, int out_size){
    const float* x      = (const float*)d_in[0];
    const float* conv_w = (const float*)d_in[1];
    const float* conv_b = (const float*)d_in[2];
    const float* kv_w   = (const float*)d_in[3];
    const float* kv_b   = (const float*)d_in[4];
    const float* q_w    = (const float*)d_in[5];
    const float* q_b    = (const float*)d_in[6];
    const float* w1     = (const float*)d_in[7];
    const float* b1m    = (const float*)d_in[8];
    const float* w2     = (const float*)d_in[9];
    const float* b2m    = (const float*)d_in[10];
    const float* g1     = (const float*)d_in[11];
    const float* b1_    = (const float*)d_in[12];
    const float* g2     = (const float*)d_in[13];
    const float* b2_    = (const float*)d_in[14];
    const float* g3     = (const float*)d_in[15];
    const float* b3_    = (const float*)d_in[16];
    const float* temp   = (const float*)d_in[17];
    const float* freqs  = (const float*)d_in[18];

    __nv_bfloat16 *cwh,*cwl,*kvwh,*kvwl,*qwh,*qwl,*w1h,*w1l,*w2h,*w2l;
    __nv_bfloat16 *xh,*xl,*kh,*kl,*vth,*vtl,*qh,*ql;
    __half *vph,*vpl;
    float *xo,*xoutg,*kv,*qlin,*attn_s,*rowsum,*colinv,*Sv,*h1;
    cudaGetSymbolAddress((void**)&cwh,  g_cwh);  cudaGetSymbolAddress((void**)&cwl,  g_cwl);
    cudaGetSymbolAddress((void**)&kvwh, g_kvwh); cudaGetSymbolAddress((void**)&kvwl, g_kvwl);
    cudaGetSymbolAddress((void**)&qwh,  g_qwh);  cudaGetSymbolAddress((void**)&qwl,  g_qwl);
    cudaGetSymbolAddress((void**)&w1h,  g_w1h);  cudaGetSymbolAddress((void**)&w1l,  g_w1l);
    cudaGetSymbolAddress((void**)&w2h,  g_w2h);  cudaGetSymbolAddress((void**)&w2l,  g_w2l);
    cudaGetSymbolAddress((void**)&xh,   g_xh);   cudaGetSymbolAddress((void**)&xl,   g_xl);
    cudaGetSymbolAddress((void**)&kh,   g_kh);   cudaGetSymbolAddress((void**)&kl,   g_kl);
    cudaGetSymbolAddress((void**)&vth,  g_vth);  cudaGetSymbolAddress((void**)&vtl,  g_vtl);
    cudaGetSymbolAddress((void**)&vph,  g_vph);  cudaGetSymbolAddress((void**)&vpl,  g_vpl);
    cudaGetSymbolAddress((void**)&qh,   g_qh);   cudaGetSymbolAddress((void**)&ql,   g_ql);
    cudaGetSymbolAddress((void**)&xo,     g_xo);
    cudaGetSymbolAddress((void**)&xoutg,  g_xout);
    cudaGetSymbolAddress((void**)&kv,     g_kv);
    cudaGetSymbolAddress((void**)&qlin,   g_qlin);
    cudaGetSymbolAddress((void**)&attn_s, g_attn);
    cudaGetSymbolAddress((void**)&rowsum, g_rowsum);
    cudaGetSymbolAddress((void**)&colinv, g_colinv);
    cudaGetSymbolAddress((void**)&Sv,     g_S);
    cudaGetSymbolAddress((void**)&h1,     g_h1);

    float* out = (float*)d_out;
    bool full = (size_t)out_size >= (size_t)XOUT_SZ + 2*ATTN_SZ;
    float* xout      = full ? out : xoutg;                       // x_out in place
    float* out_attnq = full ? out + XOUT_SZ : attn_s;
    float* out_attnk = full ? out + XOUT_SZ + ATTN_SZ : attn_s;
    __half* Eh       = (__half*)attn_s;                          // fp16 (E-1), all iters

    // ---- prologue: pack weights + pre-split x ----
    packconvT_kernel<<<(D_*CKK + 255)/256, 256>>>(conv_w, cwh, cwl);
    packT_kernel<<<(D_*2*D_ + 255)/256, 256>>>(kv_w, kvwh, kvwl, D_, 2*D_);
    packT_kernel<<<(D_*D_ + 255)/256, 256>>>(q_w, qwh, qwl, D_, D_);
    packT_kernel<<<(D_*4*D_ + 255)/256, 256>>>(w1, w1h, w1l, D_, 4*D_);
    packT_kernel<<<(4*D_*D_ + 255)/256, 256>>>(w2, w2h, w2l, 4*D_, D_);
    splitf_kernel<<<(MIN_*D_ + 255)/256, 256>>>(x, xh, xl, MIN_*D_);

    // ---- conv + first LN ----
    seed_kernel<<<(MOUT*D_ + 255)/256, 256>>>(conv_b, xo, MOUT, D_);
    mconv_kernel<<<dim3(D_/64, (MOUT+127)/128, 7), 256>>>(xh, xl, cwh, cwl, xo);
    ln_kernel<<<MOUT, D_>>>(xo, g1, b1_, xout, 0);

    // ---- kv (loop-invariant) + rose-split ----
    mgemm_pre_kernel<<<dim3(2*D_/64, MIN_/128), 256>>>(xh, xl, kvwh, kvwl, kv_b, kv, MIN_, 2*D_, D_);
    int totk = BH_*NIN*HD_;
    rose_hl_kernel<<<(totk+255)/256, 256>>>(kv, 2*D_, 0, kh, kl, NIN, GW_, 1.f, 1.f, freqs, temp, 1);
    vT_hl_kernel<<<(totk+255)/256, 256>>>(kv, vth, vtl);

    int totq = BH_*NOUT*HD_;
    for (int it = 0; it < 3; it++){
        int writeout = (it == 2 && full) ? 1 : 0;
        prep_kernel<<<(MOUT*D_ + 255)/256, 256>>>(q_b, qlin, xo, rowsum);
        mgemm_kernel<<<dim3(D_/64, (MOUT+127)/128, 2), 256>>>(xout, qwh, qwl, q_b, qlin, MOUT, D_, D_, D_/2, 0, 1);
        rose_hl_kernel<<<(totq+255)/256, 256>>>(qlin, D_, 0, qh, ql, NOUT, QG, 3.f, 3.f, freqs, temp, 0);

        mscore_kernel<<<dim3(NIN/128, (NOUT+63)/64, BH_), 256>>>(qh, ql, kh, kl, Eh, rowsum);
        rowinv_kernel<<<(BH_*NOUT + 255)/256, 256>>>(rowsum);
        colsum_kernel<<<dim3(NIN/256, BH_), 256>>>(Eh, rowsum, colinv);
        vprep_kernel<<<dim3(BH_, HD_), 256>>>(vth, vtl, colinv, vph, vpl, Sv);
        mpv_kernel<<<dim3((NOUT+63)/64, BH_, 4), 256>>>(Eh, rowsum, colinv, vph, vpl, Sv,
                                                        xo, out_attnk, out_attnq, writeout);
        ln_kernel<<<MOUT, D_>>>(xo, g2, b2_, xout, 1);

        mgemm_kernel<<<dim3(4*D_/64, (MOUT+127)/128, 1), 256>>>(xout, w1h, w1l, b1m, h1, MOUT, 4*D_, D_, D_, 1, 0);
        seed_kernel<<<(MOUT*D_ + 255)/256, 256>>>(b2m, xo, MOUT, D_);
        mgemm_kernel<<<dim3(D_/64, (MOUT+127)/128, 2), 256>>>(h1, w2h, w2l, b2m, xo, MOUT, D_, 4*D_, 2*D_, 0, 1);
        ln_kernel<<<MOUT, D_>>>(xo, g3, b3_, xout, 1);
    }
}

// round 13
// speedup vs baseline: 1.1130x; 1.1130x over previous
#include <cuda_runtime.h>
#include <cuda_bf16.h>
#include <cuda_fp16.h>
#include <math.h>
#include <stdint.h>

// ---------------- problem constants ----------------
#define B_    2
#define NIN   4096
#define NOUT  484
#define D_    384
#define H_    12
#define HD_   32
#define QG    22
#define GW_   64
#define MOUT  (B_*NOUT)   // 968
#define MIN_  (B_*NIN)    // 8192
#define BH_   (B_*H_)     // 24
#define NROT_ 16
#define LNEPS 1e-5f
#define EPSV  1.1920929e-07f
#define CKK   (49*D_)     // 18816 conv k-extent

#define XOUT_SZ  (MOUT*D_)                       // 371712
#define ATTN_SZ  ((size_t)BH_*NOUT*NIN)          // 47579136

// ---------------- scratch (device globals; no alloc allowed) ----------------
__device__ __nv_bfloat16 g_cwh[D_*CKK],  g_cwl[D_*CKK];       // conv w: [co][khw*384+ci]
__device__ __nv_bfloat16 g_kvwh[2*D_*D_], g_kvwl[2*D_*D_];
__device__ __nv_bfloat16 g_qwh[D_*D_],    g_qwl[D_*D_];
__device__ __nv_bfloat16 g_w1h[4*D_*D_],  g_w1l[4*D_*D_];
__device__ __nv_bfloat16 g_w2h[D_*4*D_],  g_w2l[D_*4*D_];
__device__ __nv_bfloat16 g_xh[MIN_*D_],   g_xl[MIN_*D_];       // pre-split input x
__device__ __nv_bfloat16 g_kh[BH_*NIN*HD_],  g_kl[BH_*NIN*HD_];
__device__ __nv_bfloat16 g_vth[BH_*HD_*NIN], g_vtl[BH_*HD_*NIN];  // [bh][d][n]
__device__ __nv_bfloat16 g_qh[BH_*NOUT*HD_], g_ql[BH_*NOUT*HD_];
__device__ float g_xo[MOUT*D_];
__device__ float g_xout[MOUT*D_];                 // fallback only
__device__ float g_kv[MIN_*2*D_];
__device__ float g_qlin[MOUT*D_];
__device__ float g_attn[(size_t)BH_*NOUT*NIN];    // fp16 (E-1) store + fallback region
__device__ float g_rowsum[BH_*NOUT];
__device__ float g_colinv[BH_*NIN];
__device__ float g_h1[MOUT*4*D_];

// ---------------- helpers ----------------
__device__ __forceinline__ float gelu_f(float x){
    return 0.5f * x * (1.0f + erff(x * 0.70710678118654752f));
}
__device__ __forceinline__ void split1(float v, __nv_bfloat16& h, __nv_bfloat16& l){
    h = __float2bfloat16(v);
    l = __float2bfloat16(v - __bfloat162float(h));
}
__device__ __forceinline__ void split4(float4 v, unsigned& h0, unsigned& h1,
                                       unsigned& l0, unsigned& l1){
    __nv_bfloat162 hx = __floats2bfloat162_rn(v.x, v.y);
    __nv_bfloat162 hz = __floats2bfloat162_rn(v.z, v.w);
    float2 fx = __bfloat1622float2(hx);
    float2 fz = __bfloat1622float2(hz);
    __nv_bfloat162 lx = __floats2bfloat162_rn(v.x - fx.x, v.y - fx.y);
    __nv_bfloat162 lz = __floats2bfloat162_rn(v.z - fz.x, v.w - fz.y);
    h0 = *(unsigned*)&hx; h1 = *(unsigned*)&hz;
    l0 = *(unsigned*)&lx; l1 = *(unsigned*)&lz;
}
// FFMA-only exp (no MUFU), rel err ~1.2e-7
__device__ __forceinline__ float exp_fast(float x){
    float t = x * 1.4426950408889634f;
    float r = t + 12582912.0f;
    int   n = __float_as_int(r) - 0x4B400000;
    float f = t - (r - 12582912.0f);
    float p =            1.5403530e-4f;
    p = fmaf(p, f, 1.3333558e-3f);
    p = fmaf(p, f, 9.6181291e-3f);
    p = fmaf(p, f, 5.5504109e-2f);
    p = fmaf(p, f, 2.4022651e-1f);
    p = fmaf(p, f, 6.9314718e-1f);
    p = fmaf(p, f, 1.0f);
    return __int_as_float(__float_as_int(p) + (n << 23));
}
__device__ __forceinline__ void mma16816(float* c, const unsigned* a, const unsigned* b){
    asm volatile("mma.sync.aligned.m16n8k16.row.col.f32.bf16.bf16.f32 "
        "{%0,%1,%2,%3},{%4,%5,%6,%7},{%8,%9},{%0,%1,%2,%3};"
        : "+f"(c[0]), "+f"(c[1]), "+f"(c[2]), "+f"(c[3])
        : "r"(a[0]), "r"(a[1]), "r"(a[2]), "r"(a[3]), "r"(b[0]), "r"(b[1]));
}

// ---------------- prologue pack kernels ----------------
__global__ void packT_kernel(const float* __restrict__ src, __nv_bfloat16* __restrict__ h,
                             __nv_bfloat16* __restrict__ l, int K, int N){
    int idx = blockIdx.x*blockDim.x + threadIdx.x;
    if (idx >= K*N) return;
    int n = idx / K, k = idx % K;
    __nv_bfloat16 hh, ll; split1(src[(size_t)k*N + n], hh, ll);
    h[idx] = hh; l[idx] = ll;
}
__global__ void packconvT_kernel(const float* __restrict__ w, __nv_bfloat16* __restrict__ h,
                                 __nv_bfloat16* __restrict__ l){
    int idx = blockIdx.x*blockDim.x + threadIdx.x;
    if (idx >= D_*CKK) return;
    int co = idx / CKK, r = idx % CKK;
    int khw = r / D_, ci = r % D_;
    __nv_bfloat16 hh, ll; split1(w[((size_t)co*D_ + ci)*49 + khw], hh, ll);
    h[idx] = hh; l[idx] = ll;
}
__global__ void splitf_kernel(const float* __restrict__ src, __nv_bfloat16* __restrict__ h,
                              __nv_bfloat16* __restrict__ l, int n){
    int i = blockIdx.x*blockDim.x + threadIdx.x;
    if (i >= n) return;
    __nv_bfloat16 hh, ll; split1(src[i], hh, ll);
    h[i] = hh; l[i] = ll;
}
__global__ void seed_kernel(const float* __restrict__ b, float* __restrict__ o, int M, int N){
    int idx = blockIdx.x*blockDim.x + threadIdx.x;
    if (idx < M*N) o[idx] = b[idx % N];
}
// per-iter prep: xo=0, qlin=q_b, rowsum=0
__global__ void prep_kernel(const float* __restrict__ qb, float* __restrict__ qlin,
                            float* __restrict__ xo, float* __restrict__ rowsum){
    int i = blockIdx.x*blockDim.x + threadIdx.x;
    if (i < MOUT*D_){ xo[i] = 0.f; qlin[i] = qb[i % D_]; }
    if (i < BH_*NOUT) rowsum[i] = 0.f;
}

// ---------------- rose (rotary) producing bf16 hi/lo directly ----------------
__global__ void rose_hl_kernel(const float* __restrict__ src, int stride, int off,
                               __nv_bfloat16* __restrict__ dh, __nv_bfloat16* __restrict__ dl,
                               int N, int Gw, float sp0, float sp1,
                               const float* __restrict__ fr, const float* __restrict__ temp,
                               int applyTemp){
    int idx = blockIdx.x*blockDim.x + threadIdx.x;
    int total = BH_ * N * HD_;
    if (idx >= total) return;
    int hd = idx & 31;
    int n  = (idx >> 5) % N;
    int bh = idx / (N*32);
    int h = bh % H_, b = bh / H_;
    const float* sp = src + ((size_t)b*N + n)*stride + off + h*HD_;
    float val;
    if (hd < NROT_){
        int m = hd >> 1, s = m >> 2, p = m & 3;
        float coord = (s == 0) ? (float)(n / Gw) * sp0 : (float)(n % Gw) * sp1;
        float ang = coord * fr[(h*2 + s)*4 + p];
        float cs, sn; sincosf(ang, &sn, &cs);
        float x1 = sp[2*m], x2 = sp[2*m+1];
        val = (hd & 1) ? (x1*sn + x2*cs) : (x1*cs - x2*sn);
    } else {
        val = sp[hd];
    }
    if (applyTemp) val *= temp[0];
    __nv_bfloat16 hh, ll; split1(val, hh, ll);
    dh[idx] = hh; dl[idx] = ll;
}
__global__ void vT_hl_kernel(const float* __restrict__ kv, __nv_bfloat16* __restrict__ th,
                             __nv_bfloat16* __restrict__ tl){
    int i = blockIdx.x*blockDim.x + threadIdx.x;
    if (i >= BH_*HD_*NIN) return;
    int n  = i % NIN;
    int d  = (i / NIN) % HD_;
    int bh = i / (NIN*HD_);
    int h = bh % H_, b = bh / H_;
    float v = kv[((size_t)b*NIN + n)*(2*D_) + D_ + h*HD_ + d];
    __nv_bfloat16 hh, ll; split1(v, hh, ll);
    th[i] = hh; tl[i] = ll;
}

// ================= HMMA bf16-split dense GEMM =================
#define ASTR 40

struct Frag { unsigned ah[2][4], al[2][4], bh[4][2], bl[4][2]; };

__device__ __forceinline__ void load_frags(Frag& f, const __nv_bfloat16* Ah, const __nv_bfloat16* Al,
                                           const __nv_bfloat16* Bh, const __nv_bfloat16* Bl,
                                           int wm, int wn, int ks, int g, int c2){
    #pragma unroll
    for (int t = 0; t < 2; t++){
        int rb = (wm*32 + t*16 + g)*ASTR + ks + c2;
        f.ah[t][0] = *(const unsigned*)(Ah + rb);
        f.ah[t][1] = *(const unsigned*)(Ah + rb + 8*ASTR);
        f.ah[t][2] = *(const unsigned*)(Ah + rb + 8);
        f.ah[t][3] = *(const unsigned*)(Ah + rb + 8*ASTR + 8);
        f.al[t][0] = *(const unsigned*)(Al + rb);
        f.al[t][1] = *(const unsigned*)(Al + rb + 8*ASTR);
        f.al[t][2] = *(const unsigned*)(Al + rb + 8);
        f.al[t][3] = *(const unsigned*)(Al + rb + 8*ASTR + 8);
    }
    #pragma unroll
    for (int u = 0; u < 4; u++){
        int nb = (wn*32 + u*8 + g)*ASTR + ks + c2;
        f.bh[u][0] = *(const unsigned*)(Bh + nb);
        f.bh[u][1] = *(const unsigned*)(Bh + nb + 8);
        f.bl[u][0] = *(const unsigned*)(Bl + nb);
        f.bl[u][1] = *(const unsigned*)(Bl + nb + 8);
    }
}
__device__ __forceinline__ void do_mmas(float (*acc)[4], const Frag& f){
    #pragma unroll
    for (int t = 0; t < 2; t++)
        #pragma unroll
        for (int u = 0; u < 4; u++){
            mma16816(acc[t*4+u], f.ah[t], f.bh[u]);
            mma16816(acc[t*4+u], f.ah[t], f.bl[u]);
            mma16816(acc[t*4+u], f.al[t], f.bh[u]);
        }
}
__device__ __forceinline__ void epi(float (*acc)[4], const float* __restrict__ bias,
                                    float* __restrict__ C, int M, int N, int m0, int n0,
                                    int wm, int wn, int g, int c2, int act, int atom){
    #pragma unroll
    for (int t = 0; t < 2; t++){
        int r0 = m0 + wm*32 + t*16 + g;
        #pragma unroll
        for (int u = 0; u < 4; u++){
            int cb = n0 + wn*32 + u*8 + c2;
            float* ac = acc[t*4+u];
            if (atom){
                if (r0 < M){
                    atomicAdd(&C[(size_t)r0*N + cb],     ac[0]);
                    atomicAdd(&C[(size_t)r0*N + cb + 1], ac[1]);
                }
                if (r0 + 8 < M){
                    atomicAdd(&C[(size_t)(r0+8)*N + cb],     ac[2]);
                    atomicAdd(&C[(size_t)(r0+8)*N + cb + 1], ac[3]);
                }
            } else {
                float b0 = bias[cb], b1 = bias[cb+1];
                float o0 = ac[0]+b0, o1 = ac[1]+b1, o2 = ac[2]+b0, o3 = ac[3]+b1;
                if (act){ o0=gelu_f(o0); o1=gelu_f(o1); o2=gelu_f(o2); o3=gelu_f(o3); }
                if (r0 < M){ C[(size_t)r0*N + cb] = o0; C[(size_t)r0*N + cb + 1] = o1; }
                if (r0 + 8 < M){ C[(size_t)(r0+8)*N + cb] = o2; C[(size_t)(r0+8)*N + cb + 1] = o3; }
            }
        }
    }
}
__device__ __forceinline__ void fillA(__nv_bfloat16* Ah, __nv_bfloat16* Al,
                                      const float* __restrict__ A, int M, int K,
                                      int m0, int k0, int tid){
    #pragma unroll
    for (int i = 0; i < 4; i++){
        int e = tid + i*256;
        int row = e >> 3, kg = (e & 7)*4;
        float4 v = (m0+row < M) ? *(const float4*)(A + (size_t)(m0+row)*K + k0 + kg)
                                : make_float4(0.f,0.f,0.f,0.f);
        unsigned h0,h1,l0,l1; split4(v, h0,h1,l0,l1);
        unsigned* ph = (unsigned*)&Ah[row*ASTR + kg];
        unsigned* pl = (unsigned*)&Al[row*ASTR + kg];
        ph[0]=h0; ph[1]=h1; pl[0]=l0; pl[1]=l1;
    }
}
__device__ __forceinline__ void fillB(__nv_bfloat16* Bh, __nv_bfloat16* Bl,
                                      const __nv_bfloat16* __restrict__ Wh,
                                      const __nv_bfloat16* __restrict__ Wl,
                                      size_t rowbase, int Kst, int n0, int tid){
    int n  = tid >> 2;
    int kb = (tid & 3)*8;
    const unsigned* ph = (const unsigned*)Wh + ((rowbase + (size_t)(n0+n)*Kst + kb) >> 1);
    const unsigned* pl = (const unsigned*)Wl + ((rowbase + (size_t)(n0+n)*Kst + kb) >> 1);
    unsigned* sh = (unsigned*)&Bh[n*ASTR + kb];
    unsigned* sl = (unsigned*)&Bl[n*ASTR + kb];
    #pragma unroll
    for (int j = 0; j < 4; j++){ sh[j] = ph[j]; sl[j] = pl[j]; }
}

__global__ __launch_bounds__(256, 2)
void mgemm_kernel(const float* __restrict__ A, const __nv_bfloat16* __restrict__ Wh,
                  const __nv_bfloat16* __restrict__ Wl,
                  const float* __restrict__ bias, float* __restrict__ C,
                  int M, int N, int K, int kSlice, int act, int atom){
    __shared__ __align__(16) __nv_bfloat16 Ah[128*ASTR], Al[128*ASTR];
    __shared__ __align__(16) __nv_bfloat16 Bh[64*ASTR],  Bl[64*ASTR];
    int tid = threadIdx.x, lane = tid & 31, wid = tid >> 5;
    int wm = wid >> 1, wn = wid & 1;
    int g = lane >> 2, c2 = (lane & 3)*2;
    int m0 = blockIdx.y*128, n0 = blockIdx.x*64;
    int kb0 = blockIdx.z*kSlice, kend = kb0 + kSlice;
    float acc[8][4] = {};
    for (int k0 = kb0; k0 < kend; k0 += 32){
        fillA(Ah, Al, A, M, K, m0, k0, tid);
        fillB(Bh, Bl, Wh, Wl, (size_t)k0, K, n0, tid);
        __syncthreads();
        #pragma unroll
        for (int ks = 0; ks < 32; ks += 16){
            Frag f;
            load_frags(f, Ah, Al, Bh, Bl, wm, wn, ks, g, c2);
            do_mmas(acc, f);
        }
        __syncthreads();
    }
    epi(acc, bias, C, M, N, m0, n0, wm, wn, g, c2, act, atom);
}

// A pre-split variant (for kv GEMM on x)
__global__ __launch_bounds__(256, 2)
void mgemm_pre_kernel(const __nv_bfloat16* __restrict__ Xh, const __nv_bfloat16* __restrict__ Xl,
                      const __nv_bfloat16* __restrict__ Wh, const __nv_bfloat16* __restrict__ Wl,
                      const float* __restrict__ bias, float* __restrict__ C,
                      int M, int N, int K){
    __shared__ __align__(16) __nv_bfloat16 Ah[128*ASTR], Al[128*ASTR];
    __shared__ __align__(16) __nv_bfloat16 Bh[64*ASTR],  Bl[64*ASTR];
    int tid = threadIdx.x, lane = tid & 31, wid = tid >> 5;
    int wm = wid >> 1, wn = wid & 1;
    int g = lane >> 2, c2 = (lane & 3)*2;
    int m0 = blockIdx.y*128, n0 = blockIdx.x*64;
    float acc[8][4] = {};
    for (int k0 = 0; k0 < K; k0 += 32){
        #pragma unroll
        for (int i = 0; i < 4; i++){
            int e = tid + i*256;
            int row = e >> 3, kg = (e & 7)*4;
            size_t off = (size_t)(m0+row)*K + k0 + kg;
            uint2 h = make_uint2(0u,0u), l = h;
            if (m0+row < M){
                h = *(const uint2*)(Xh + off);
                l = *(const uint2*)(Xl + off);
            }
            *(uint2*)&Ah[row*ASTR + kg] = h;
            *(uint2*)&Al[row*ASTR + kg] = l;
        }
        fillB(Bh, Bl, Wh, Wl, (size_t)k0, K, n0, tid);
        __syncthreads();
        #pragma unroll
        for (int ks = 0; ks < 32; ks += 16){
            Frag f;
            load_frags(f, Ah, Al, Bh, Bl, wm, wn, ks, g, c2);
            do_mmas(acc, f);
        }
        __syncthreads();
    }
    epi(acc, bias, C, M, N, m0, n0, wm, wn, g, c2, 0, 0);
}

// conv implicit GEMM with pre-split x; grid.z = 7 kh-slices, atomic epilogue
// occupancy 3 -> 444-CTA capacity -> 336-block grid runs in a single wave
__global__ __launch_bounds__(256, 3)
void mconv_kernel(const __nv_bfloat16* __restrict__ Xh, const __nv_bfloat16* __restrict__ Xl,
                  const __nv_bfloat16* __restrict__ Wh, const __nv_bfloat16* __restrict__ Wl,
                  float* __restrict__ C){
    __shared__ __align__(16) __nv_bfloat16 Ah[128*ASTR], Al[128*ASTR];
    __shared__ __align__(16) __nv_bfloat16 Bh[64*ASTR],  Bl[64*ASTR];
    int tid = threadIdx.x, lane = tid & 31, wid = tid >> 5;
    int wm = wid >> 1, wn = wid & 1;
    int g = lane >> 2, c2 = (lane & 3)*2;
    int m0 = blockIdx.y*128, n0 = blockIdx.x*64;
    int slice = blockIdx.z;
    float acc[8][4] = {};
    for (int kc = 0; kc < 7*D_; kc += 32){
        int khw = slice*7 + kc/D_;
        int cib = kc % D_;
        int kh = khw/7, kw = khw%7;
        #pragma unroll
        for (int i = 0; i < 4; i++){
            int e = tid + i*256;
            int row = e >> 3, kg = (e & 7)*4;
            int m = m0 + row;
            uint2 h = make_uint2(0u,0u), l = h;
            if (m < MOUT){
                int bb = m / NOUT, rr = m % NOUT;
                int oh = rr / QG, ow = rr % QG;
                int ih = oh*3 - 3 + kh, iw = ow*3 - 3 + kw;
                if ((unsigned)ih < 64u && (unsigned)iw < 64u){
                    size_t off = ((size_t)(bb*NIN + ih*GW_ + iw))*D_ + cib + kg;
                    h = *(const uint2*)(Xh + off);
                    l = *(const uint2*)(Xl + off);
                }
            }
            *(uint2*)&Ah[row*ASTR + kg] = h;
            *(uint2*)&Al[row*ASTR + kg] = l;
        }
        fillB(Bh, Bl, Wh, Wl, (size_t)(khw*D_ + cib), CKK, n0, tid);
        __syncthreads();
        #pragma unroll
        for (int ks = 0; ks < 32; ks += 16){
            Frag f;
            load_frags(f, Ah, Al, Bh, Bl, wm, wn, ks, g, c2);
            do_mmas(acc, f);
        }
        __syncthreads();
    }
    epi(acc, (const float*)0, C, MOUT, D_, m0, n0, wm, wn, g, c2, 0, 1);
}

// ---------------- one-pass layernorm over D=384, optional residual-add -------------
__global__ void ln_kernel(const float* __restrict__ X, const float* __restrict__ g,
                          const float* __restrict__ bt, float* __restrict__ out, int add){
    int row = blockIdx.x, tid = threadIdx.x;
    float x = X[(size_t)row*D_ + tid];
    __shared__ float w1s[12], w2s[12];
    float s1 = x, s2 = x*x;
    #pragma unroll
    for (int o = 16; o > 0; o >>= 1){
        s1 += __shfl_down_sync(0xffffffffu, s1, o);
        s2 += __shfl_down_sync(0xffffffffu, s2, o);
    }
    if ((tid & 31) == 0){ w1s[tid >> 5] = s1; w2s[tid >> 5] = s2; }
    __syncthreads();
    if (tid == 0){
        float t1 = 0.f, t2 = 0.f;
        #pragma unroll
        for (int i = 0; i < 12; i++){ t1 += w1s[i]; t2 += w2s[i]; }
        w1s[0] = t1; w2s[0] = t2;
    }
    __syncthreads();
    float mu  = w1s[0] * (1.0f/D_);
    float var = w2s[0] * (1.0f/D_) - mu*mu;
    float y = (x - mu) * rsqrtf(var + LNEPS) * g[tid] + bt[tid];
    size_t o_ = (size_t)row*D_ + tid;
    out[o_] = add ? (out[o_] + y) : y;
}

// ======== HMMA scores: E = exp(Q K^T); store d = E-1 as fp16; fused row-sum ========
__global__ __launch_bounds__(256)
void mscore_kernel(const __nv_bfloat16* __restrict__ Qh, const __nv_bfloat16* __restrict__ Ql,
                   const __nv_bfloat16* __restrict__ Kh, const __nv_bfloat16* __restrict__ Kl,
                   __half* __restrict__ Eh, float* __restrict__ rowsum){
    __shared__ __align__(16) __nv_bfloat16 Qhs[64*ASTR], Qls[64*ASTR];
    __shared__ __align__(16) __nv_bfloat16 Khs[128*ASTR], Kls[128*ASTR];
    __shared__ float rs[64];
    int tid = threadIdx.x, lane = tid & 31, wid = tid >> 5;
    int wq = wid >> 2, wk = wid & 3;
    int g = lane >> 2, c2 = (lane & 3)*2;
    int kt = blockIdx.x*128, q0 = blockIdx.y*64, bh = blockIdx.z;
    if (tid < 64) rs[tid] = 0.f;
    {
        int row = tid >> 2, kb = (tid & 3)*8;
        unsigned* sh = (unsigned*)&Qhs[row*ASTR + kb];
        unsigned* sl = (unsigned*)&Qls[row*ASTR + kb];
        if (q0 + row < NOUT){
            size_t e32 = ((size_t)(bh*NOUT + q0 + row)*HD_ + kb) >> 1;
            const unsigned* ph = (const unsigned*)Qh + e32;
            const unsigned* pl = (const unsigned*)Ql + e32;
            #pragma unroll
            for (int j = 0; j < 4; j++){ sh[j] = ph[j]; sl[j] = pl[j]; }
        } else {
            #pragma unroll
            for (int j = 0; j < 4; j++){ sh[j] = 0u; sl[j] = 0u; }
        }
    }
    {
        int row = tid >> 1, kb = (tid & 1)*16;
        size_t e32 = ((size_t)(bh*NIN + kt + row)*HD_ + kb) >> 1;
        const unsigned* ph = (const unsigned*)Kh + e32;
        const unsigned* pl = (const unsigned*)Kl + e32;
        unsigned* sh = (unsigned*)&Khs[row*ASTR + kb];
        unsigned* sl = (unsigned*)&Kls[row*ASTR + kb];
        #pragma unroll
        for (int j = 0; j < 8; j++){ sh[j] = ph[j]; sl[j] = pl[j]; }
    }
    __syncthreads();
    float acc[2][4][4] = {};
    #pragma unroll
    for (int ks = 0; ks < 32; ks += 16){
        unsigned ah[2][4], al[2][4], bhf[4][2], blf[4][2];
        #pragma unroll
        for (int t = 0; t < 2; t++){
            int rb = (wq*32 + t*16 + g)*ASTR + ks + c2;
            ah[t][0] = *(const unsigned*)(Qhs + rb);
            ah[t][1] = *(const unsigned*)(Qhs + rb + 8*ASTR);
            ah[t][2] = *(const unsigned*)(Qhs + rb + 8);
            ah[t][3] = *(const unsigned*)(Qhs + rb + 8*ASTR + 8);
            al[t][0] = *(const unsigned*)(Qls + rb);
            al[t][1] = *(const unsigned*)(Qls + rb + 8*ASTR);
            al[t][2] = *(const unsigned*)(Qls + rb + 8);
            al[t][3] = *(const unsigned*)(Qls + rb + 8*ASTR + 8);
        }
        #pragma unroll
        for (int u = 0; u < 4; u++){
            int nb = (wk*32 + u*8 + g)*ASTR + ks + c2;
            bhf[u][0] = *(const unsigned*)(Khs + nb);
            bhf[u][1] = *(const unsigned*)(Khs + nb + 8);
            blf[u][0] = *(const unsigned*)(Kls + nb);
            blf[u][1] = *(const unsigned*)(Kls + nb + 8);
        }
        #pragma unroll
        for (int t = 0; t < 2; t++)
            #pragma unroll
            for (int u = 0; u < 4; u++){
                mma16816(acc[t][u], ah[t], bhf[u]);
                mma16816(acc[t][u], ah[t], blf[u]);
                mma16816(acc[t][u], al[t], bhf[u]);
            }
    }
    #pragma unroll
    for (int t = 0; t < 2; t++){
        int lr = wq*32 + t*16 + g;
        int r  = q0 + lr;
        float s0 = 0.f, s1 = 0.f;
        #pragma unroll
        for (int u = 0; u < 4; u++){
            int col = kt + wk*32 + u*8 + c2;
            float e0 = exp_fast(acc[t][u][0]), e1 = exp_fast(acc[t][u][1]);
            float e2 = exp_fast(acc[t][u][2]), e3 = exp_fast(acc[t][u][3]);
            __half2 v0 = __floats2half2_rn(e0 - 1.0f, e1 - 1.0f);
            __half2 v1 = __floats2half2_rn(e2 - 1.0f, e3 - 1.0f);
            if (r < NOUT)
                *(__half2*)(Eh + (size_t)(bh*NOUT + r)*NIN + col) = v0;
            if (r + 8 < NOUT)
                *(__half2*)(Eh + (size_t)(bh*NOUT + r + 8)*NIN + col) = v1;
            s0 += e0 + e1; s1 += e2 + e3;
        }
        s0 += __shfl_xor_sync(0xffffffffu, s0, 1);
        s0 += __shfl_xor_sync(0xffffffffu, s0, 2);
        s1 += __shfl_xor_sync(0xffffffffu, s1, 1);
        s1 += __shfl_xor_sync(0xffffffffu, s1, 2);
        if ((lane & 3) == 0){
            atomicAdd(&rs[lr], s0);
            atomicAdd(&rs[lr + 8], s1);
        }
    }
    __syncthreads();
    if (tid < 64 && q0 + tid < NOUT)
        atomicAdd(rowsum + bh*NOUT + q0 + tid, rs[tid]);
}

__global__ void rowinv_kernel(float* __restrict__ rowsum){
    int i = blockIdx.x*blockDim.x + threadIdx.x;
    if (i < BH_*NOUT) rowsum[i] = 1.f / rowsum[i];
}

__global__ void colsum_kernel(const __half* __restrict__ Eh, const float* __restrict__ rinv,
                              float* __restrict__ colinv){
    int bh = blockIdx.y;
    int col = blockIdx.x*256 + threadIdx.x;
    const __half* a = Eh + (size_t)bh*NOUT*NIN + col;
    const float* ri = rinv + bh*NOUT;
    float s = 0.f;
    #pragma unroll 4
    for (int qi = 0; qi < NOUT; qi++)
        s += (1.0f + __half2float(a[(size_t)qi*NIN])) * __ldg(ri + qi);
    colinv[bh*NIN + col] = 1.f / (s + EPSV);
}

// ======== HMMA PV: upd += (E*rinv*colinv) @ V, split-K=4, atomic epilogue ========
// writeout: also emit attn_k = E*rinv and attn_q = E*rinv*colinv (fp32) on last iter.
#define PSTR 72
__global__ __launch_bounds__(256)
void mpv_kernel(const __half* __restrict__ Eh,
                const float* __restrict__ rinv, const float* __restrict__ colinv,
                const __nv_bfloat16* __restrict__ Vth, const __nv_bfloat16* __restrict__ Vtl,
                float* __restrict__ out, float* __restrict__ outk, float* __restrict__ outq,
                int writeout){
    __shared__ __align__(16) __nv_bfloat16 Ahs[64*PSTR], Als[64*PSTR];
    __shared__ __align__(16) __nv_bfloat16 Vhs[32*PSTR], Vls[32*PSTR];
    int tid = threadIdx.x, lane = tid & 31, wid = tid >> 5;
    int wq = wid >> 1, wd = wid & 1;
    int g = lane >> 2, c2 = (lane & 3)*2;
    int q0 = blockIdx.x*64, bh = blockIdx.y;
    int ks0 = blockIdx.z*1024;
    float acc[2][4] = {};
    int frow = tid >> 4, fcol = (tid & 15)*4;
    float rv[4];
    #pragma unroll
    for (int i = 0; i < 4; i++){
        int r = q0 + frow + i*16;
        rv[i] = (r < NOUT) ? rinv[bh*NOUT + r] : 0.f;
    }
    for (int c = 0; c < 16; c++){
        int k0 = ks0 + c*64;
        #pragma unroll
        for (int i = 0; i < 4; i++){
            int row = frow + i*16;
            int r = q0 + row;
            float4 e = make_float4(0.f,0.f,0.f,0.f);
            size_t base = (size_t)(bh*NOUT + (r < NOUT ? r : 0))*NIN + k0 + fcol;
            if (r < NOUT){
                uint2 u = *(const uint2*)(Eh + base);
                float2 f0 = __half22float2(*(__half2*)&u.x);
                float2 f1 = __half22float2(*(__half2*)&u.y);
                e = make_float4(1.0f + f0.x, 1.0f + f0.y, 1.0f + f1.x, 1.0f + f1.y);
            }
            float4 cv = *(const float4*)(colinv + bh*NIN + k0 + fcol);
            float4 a;
            a.x = e.x*rv[i]*cv.x; a.y = e.y*rv[i]*cv.y;
            a.z = e.z*rv[i]*cv.z; a.w = e.w*rv[i]*cv.w;
            if (writeout && r < NOUT){
                float4 ak;
                ak.x = e.x*rv[i]; ak.y = e.y*rv[i];
                ak.z = e.z*rv[i]; ak.w = e.w*rv[i];
                *(float4*)(outk + base) = ak;
                *(float4*)(outq + base) = a;
            }
            unsigned h0,h1,l0,l1; split4(a, h0,h1,l0,l1);
            unsigned* ph = (unsigned*)&Ahs[row*PSTR + fcol];
            unsigned* pl = (unsigned*)&Als[row*PSTR + fcol];
            ph[0]=h0; ph[1]=h1; pl[0]=l0; pl[1]=l1;
        }
        {
            int d = tid >> 3, kb = (tid & 7)*8;
            size_t e32 = ((size_t)(bh*HD_ + d)*NIN + k0 + kb) >> 1;
            const unsigned* ph = (const unsigned*)Vth + e32;
            const unsigned* pl = (const unsigned*)Vtl + e32;
            unsigned* sh = (unsigned*)&Vhs[d*PSTR + kb];
            unsigned* sl = (unsigned*)&Vls[d*PSTR + kb];
            #pragma unroll
            for (int j = 0; j < 4; j++){ sh[j] = ph[j]; sl[j] = pl[j]; }
        }
        __syncthreads();
        #pragma unroll
        for (int ks = 0; ks < 64; ks += 16){
            unsigned a_h[4], a_l[4];
            int rb = (wq*16 + g)*PSTR + ks + c2;
            a_h[0] = *(const unsigned*)(Ahs + rb);
            a_h[1] = *(const unsigned*)(Ahs + rb + 8*PSTR);
            a_h[2] = *(const unsigned*)(Ahs + rb + 8);
            a_h[3] = *(const unsigned*)(Ahs + rb + 8*PSTR + 8);
            a_l[0] = *(const unsigned*)(Als + rb);
            a_l[1] = *(const unsigned*)(Als + rb + 8*PSTR);
            a_l[2] = *(const unsigned*)(Als + rb + 8);
            a_l[3] = *(const unsigned*)(Als + rb + 8*PSTR + 8);
            #pragma unroll
            for (int u = 0; u < 2; u++){
                unsigned b_h[2], b_l[2];
                int nb = (wd*16 + u*8 + g)*PSTR + ks + c2;
                b_h[0] = *(const unsigned*)(Vhs + nb);
                b_h[1] = *(const unsigned*)(Vhs + nb + 8);
                b_l[0] = *(const unsigned*)(Vls + nb);
                b_l[1] = *(const unsigned*)(Vls + nb + 8);
                mma16816(acc[u], a_h, b_h);
                mma16816(acc[u], a_h, b_l);
                mma16816(acc[u], a_l, b_h);
            }
        }
        __syncthreads();
    }
    int b = bh / H_, h = bh % H_;
    int r0 = q0 + wq*16 + g;
    #pragma unroll
    for (int u = 0; u < 2; u++){
        int col = h*HD_ + wd*16 + u*8 + c2;
        if (r0 < NOUT){
            atomicAdd(out + (size_t)(b*NOUT + r0)*D_ + col,     acc[u][0]);
            atomicAdd(out + (size_t)(b*NOUT + r0)*D_ + col + 1, acc[u][1]);
        }
        if (r0 + 8 < NOUT){
            atomicAdd(out + (size_t)(b*NOUT + r0 + 8)*D_ + col,     acc[u][2]);
            atomicAdd(out + (size_t)(b*NOUT + r0 + 8)*D_ + col + 1, acc[u][3]);
        }
    }
}

// ---------------- host orchestration ----------------------------------------------
extern "C" void kernel_launch(void* const* d_in, const int* in_sizes, int n_in,
                              void* d_out, int out_size){
    const float* x      = (const float*)d_in[0];
    const float* conv_w = (const float*)d_in[1];
    const float* conv_b = (const float*)d_in[2];
    const float* kv_w   = (const float*)d_in[3];
    const float* kv_b   = (const float*)d_in[4];
    const float* q_w    = (const float*)d_in[5];
    const float* q_b    = (const float*)d_in[6];
    const float* w1     = (const float*)d_in[7];
    const float* b1m    = (const float*)d_in[8];
    const float* w2     = (const float*)d_in[9];
    const float* b2m    = (const float*)d_in[10];
    const float* g1     = (const float*)d_in[11];
    const float* b1_    = (const float*)d_in[12];
    const float* g2     = (const float*)d_in[13];
    const float* b2_    = (const float*)d_in[14];
    const float* g3     = (const float*)d_in[15];
    const float* b3_    = (const float*)d_in[16];
    const float* temp   = (const float*)d_in[17];
    const float* freqs  = (const float*)d_in[18];

    __nv_bfloat16 *cwh,*cwl,*kvwh,*kvwl,*qwh,*qwl,*w1h,*w1l,*w2h,*w2l;
    __nv_bfloat16 *xh,*xl,*kh,*kl,*vth,*vtl,*qh,*ql;
    float *xo,*xoutg,*kv,*qlin,*attn_s,*rowsum,*colinv,*h1;
    cudaGetSymbolAddress((void**)&cwh,  g_cwh);  cudaGetSymbolAddress((void**)&cwl,  g_cwl);
    cudaGetSymbolAddress((void**)&kvwh, g_kvwh); cudaGetSymbolAddress((void**)&kvwl, g_kvwl);
    cudaGetSymbolAddress((void**)&qwh,  g_qwh);  cudaGetSymbolAddress((void**)&qwl,  g_qwl);
    cudaGetSymbolAddress((void**)&w1h,  g_w1h);  cudaGetSymbolAddress((void**)&w1l,  g_w1l);
    cudaGetSymbolAddress((void**)&w2h,  g_w2h);  cudaGetSymbolAddress((void**)&w2l,  g_w2l);
    cudaGetSymbolAddress((void**)&xh,   g_xh);   cudaGetSymbolAddress((void**)&xl,   g_xl);
    cudaGetSymbolAddress((void**)&kh,   g_kh);   cudaGetSymbolAddress((void**)&kl,   g_kl);
    cudaGetSymbolAddress((void**)&vth,  g_vth);  cudaGetSymbolAddress((void**)&vtl,  g_vtl);
    cudaGetSymbolAddress((void**)&qh,   g_qh);   cudaGetSymbolAddress((void**)&ql,   g_ql);
    cudaGetSymbolAddress((void**)&xo,     g_xo);
    cudaGetSymbolAddress((void**)&xoutg,  g_xout);
    cudaGetSymbolAddress((void**)&kv,     g_kv);
    cudaGetSymbolAddress((void**)&qlin,   g_qlin);
    cudaGetSymbolAddress((void**)&attn_s, g_attn);
    cudaGetSymbolAddress((void**)&rowsum, g_rowsum);
    cudaGetSymbolAddress((void**)&colinv, g_colinv);
    cudaGetSymbolAddress((void**)&h1,     g_h1);

    float* out = (float*)d_out;
    bool full = (size_t)out_size >= (size_t)XOUT_SZ + 2*ATTN_SZ;
    float* xout      = full ? out : xoutg;                       // x_out in place
    float* out_attnq = full ? out + XOUT_SZ : attn_s;
    float* out_attnk = full ? out + XOUT_SZ + ATTN_SZ : attn_s;
    __half* Eh       = (__half*)attn_s;                          // fp16 (E-1), all iters

    // ---- prologue: pack weights + pre-split x ----
    packconvT_kernel<<<(D_*CKK + 255)/256, 256>>>(conv_w, cwh, cwl);
    packT_kernel<<<(D_*2*D_ + 255)/256, 256>>>(kv_w, kvwh, kvwl, D_, 2*D_);
    packT_kernel<<<(D_*D_ + 255)/256, 256>>>(q_w, qwh, qwl, D_, D_);
    packT_kernel<<<(D_*4*D_ + 255)/256, 256>>>(w1, w1h, w1l, D_, 4*D_);
    packT_kernel<<<(4*D_*D_ + 255)/256, 256>>>(w2, w2h, w2l, 4*D_, D_);
    splitf_kernel<<<(MIN_*D_ + 255)/256, 256>>>(x, xh, xl, MIN_*D_);

    // ---- conv + first LN ----
    seed_kernel<<<(MOUT*D_ + 255)/256, 256>>>(conv_b, xo, MOUT, D_);
    mconv_kernel<<<dim3(D_/64, (MOUT+127)/128, 7), 256>>>(xh, xl, cwh, cwl, xo);
    ln_kernel<<<MOUT, D_>>>(xo, g1, b1_, xout, 0);

    // ---- kv (loop-invariant) + rose-split ----
    mgemm_pre_kernel<<<dim3(2*D_/64, MIN_/128), 256>>>(xh, xl, kvwh, kvwl, kv_b, kv, MIN_, 2*D_, D_);
    int totk = BH_*NIN*HD_;
    rose_hl_kernel<<<(totk+255)/256, 256>>>(kv, 2*D_, 0, kh, kl, NIN, GW_, 1.f, 1.f, freqs, temp, 1);
    vT_hl_kernel<<<(totk+255)/256, 256>>>(kv, vth, vtl);

    int totq = BH_*NOUT*HD_;
    for (int it = 0; it < 3; it++){
        int writeout = (it == 2 && full) ? 1 : 0;
        prep_kernel<<<(MOUT*D_ + 255)/256, 256>>>(q_b, qlin, xo, rowsum);
        mgemm_kernel<<<dim3(D_/64, (MOUT+127)/128, 2), 256>>>(xout, qwh, qwl, q_b, qlin, MOUT, D_, D_, D_/2, 0, 1);
        rose_hl_kernel<<<(totq+255)/256, 256>>>(qlin, D_, 0, qh, ql, NOUT, QG, 3.f, 3.f, freqs, temp, 0);

        mscore_kernel<<<dim3(NIN/128, (NOUT+63)/64, BH_), 256>>>(qh, ql, kh, kl, Eh, rowsum);
        rowinv_kernel<<<(BH_*NOUT + 255)/256, 256>>>(rowsum);
        colsum_kernel<<<dim3(NIN/256, BH_), 256>>>(Eh, rowsum, colinv);
        mpv_kernel<<<dim3((NOUT+63)/64, BH_, 4), 256>>>(Eh, rowsum, colinv, vth, vtl,
                                                        xo, out_attnk, out_attnq, writeout);
        ln_kernel<<<MOUT, D_>>>(xo, g2, b2_, xout, 1);

        mgemm_kernel<<<dim3(4*D_/64, (MOUT+127)/128, 1), 256>>>(xout, w1h, w1l, b1m, h1, MOUT, 4*D_, D_, D_, 1, 0);
        seed_kernel<<<(MOUT*D_ + 255)/256, 256>>>(b2m, xo, MOUT, D_);
        mgemm_kernel<<<dim3(D_/64, (MOUT+127)/128, 2), 256>>>(h1, w2h, w2l, b2m, xo, MOUT, D_, 4*D_, 2*D_, 0, 1);
        ln_kernel<<<MOUT, D_>>>(xo, g3, b3_, xout, 1);
    }
}

// round 15
// speedup vs baseline: 1.1987x; 1.0770x over previous
#include <cuda_runtime.h>
#include <cuda_bf16.h>
#include <cuda_fp16.h>
#include <math.h>
#include <stdint.h>

// ---------------- problem constants ----------------
#define B_    2
#define NIN   4096
#define NOUT  484
#define D_    384
#define H_    12
#define HD_   32
#define QG    22
#define GW_   64
#define MOUT  (B_*NOUT)   // 968
#define MIN_  (B_*NIN)    // 8192
#define BH_   (B_*H_)     // 24
#define NROT_ 16
#define LNEPS 1e-5f
#define EPSV  1.1920929e-07f
#define CKK   (49*D_)     // 18816 conv k-extent

#define XOUT_SZ  (MOUT*D_)                       // 371712
#define ATTN_SZ  ((size_t)BH_*NOUT*NIN)          // 47579136

// ---------------- scratch (device globals; no alloc allowed) ----------------
__device__ __nv_bfloat16 g_cwh[D_*CKK],  g_cwl[D_*CKK];       // conv w: [co][khw*384+ci]
__device__ __nv_bfloat16 g_kvwh[2*D_*D_], g_kvwl[2*D_*D_];
__device__ __nv_bfloat16 g_qwh[D_*D_],    g_qwl[D_*D_];
__device__ __nv_bfloat16 g_w1h[4*D_*D_],  g_w1l[4*D_*D_];
__device__ __nv_bfloat16 g_w2h[D_*4*D_],  g_w2l[D_*4*D_];
__device__ __nv_bfloat16 g_xh[MIN_*D_],   g_xl[MIN_*D_];       // pre-split input x
__device__ __nv_bfloat16 g_kh[BH_*NIN*HD_],  g_kl[BH_*NIN*HD_];
__device__ __nv_bfloat16 g_vth[BH_*HD_*NIN], g_vtl[BH_*HD_*NIN];  // [bh][d][n]
__device__ __nv_bfloat16 g_qh[BH_*NOUT*HD_], g_ql[BH_*NOUT*HD_];
__device__ float g_xo[MOUT*D_];
__device__ float g_xout[MOUT*D_];                 // fallback only
__device__ float g_kv[MIN_*2*D_];
__device__ float g_qlin[MOUT*D_];
__device__ float g_attn[(size_t)BH_*NOUT*NIN];    // fp16 (E-1) store + fallback region
__device__ float g_rowsum[BH_*NOUT];
__device__ float g_colinv[BH_*NIN];
__device__ float g_h1[MOUT*4*D_];

// ---------------- helpers ----------------
__device__ __forceinline__ float gelu_f(float x){
    return 0.5f * x * (1.0f + erff(x * 0.70710678118654752f));
}
__device__ __forceinline__ void split1(float v, __nv_bfloat16& h, __nv_bfloat16& l){
    h = __float2bfloat16(v);
    l = __float2bfloat16(v - __bfloat162float(h));
}
__device__ __forceinline__ void split4(float4 v, unsigned& h0, unsigned& h1,
                                       unsigned& l0, unsigned& l1){
    __nv_bfloat162 hx = __floats2bfloat162_rn(v.x, v.y);
    __nv_bfloat162 hz = __floats2bfloat162_rn(v.z, v.w);
    float2 fx = __bfloat1622float2(hx);
    float2 fz = __bfloat1622float2(hz);
    __nv_bfloat162 lx = __floats2bfloat162_rn(v.x - fx.x, v.y - fx.y);
    __nv_bfloat162 lz = __floats2bfloat162_rn(v.z - fz.x, v.w - fz.y);
    h0 = *(unsigned*)&hx; h1 = *(unsigned*)&hz;
    l0 = *(unsigned*)&lx; l1 = *(unsigned*)&lz;
}
// FFMA-only exp (no MUFU), rel err ~1.2e-7
__device__ __forceinline__ float exp_fast(float x){
    float t = x * 1.4426950408889634f;
    float r = t + 12582912.0f;
    int   n = __float_as_int(r) - 0x4B400000;
    float f = t - (r - 12582912.0f);
    float p =            1.5403530e-4f;
    p = fmaf(p, f, 1.3333558e-3f);
    p = fmaf(p, f, 9.6181291e-3f);
    p = fmaf(p, f, 5.5504109e-2f);
    p = fmaf(p, f, 2.4022651e-1f);
    p = fmaf(p, f, 6.9314718e-1f);
    p = fmaf(p, f, 1.0f);
    return __int_as_float(__float_as_int(p) + (n << 23));
}
__device__ __forceinline__ void mma16816(float* c, const unsigned* a, const unsigned* b){
    asm volatile("mma.sync.aligned.m16n8k16.row.col.f32.bf16.bf16.f32 "
        "{%0,%1,%2,%3},{%4,%5,%6,%7},{%8,%9},{%0,%1,%2,%3};"
        : "+f"(c[0]), "+f"(c[1]), "+f"(c[2]), "+f"(c[3])
        : "r"(a[0]), "r"(a[1]), "r"(a[2]), "r"(a[3]), "r"(b[0]), "r"(b[1]));
}

// ---------------- prologue pack kernels ----------------
__global__ void packT_kernel(const float* __restrict__ src, __nv_bfloat16* __restrict__ h,
                             __nv_bfloat16* __restrict__ l, int K, int N){
    int idx = blockIdx.x*blockDim.x + threadIdx.x;
    if (idx >= K*N) return;
    int n = idx / K, k = idx % K;
    __nv_bfloat16 hh, ll; split1(src[(size_t)k*N + n], hh, ll);
    h[idx] = hh; l[idx] = ll;
}
__global__ void packconvT_kernel(const float* __restrict__ w, __nv_bfloat16* __restrict__ h,
                                 __nv_bfloat16* __restrict__ l){
    int idx = blockIdx.x*blockDim.x + threadIdx.x;
    if (idx >= D_*CKK) return;
    int co = idx / CKK, r = idx % CKK;
    int khw = r / D_, ci = r % D_;
    __nv_bfloat16 hh, ll; split1(w[((size_t)co*D_ + ci)*49 + khw], hh, ll);
    h[idx] = hh; l[idx] = ll;
}
__global__ void splitf_kernel(const float* __restrict__ src, __nv_bfloat16* __restrict__ h,
                              __nv_bfloat16* __restrict__ l, int n){
    int i = blockIdx.x*blockDim.x + threadIdx.x;
    if (i >= n) return;
    __nv_bfloat16 hh, ll; split1(src[i], hh, ll);
    h[i] = hh; l[i] = ll;
}
__global__ void seed_kernel(const float* __restrict__ b, float* __restrict__ o, int M, int N){
    int idx = blockIdx.x*blockDim.x + threadIdx.x;
    if (idx < M*N) o[idx] = b[idx % N];
}
// per-iter prep: xo=0, qlin=q_b, rowsum=0
__global__ void prep_kernel(const float* __restrict__ qb, float* __restrict__ qlin,
                            float* __restrict__ xo, float* __restrict__ rowsum){
    int i = blockIdx.x*blockDim.x + threadIdx.x;
    if (i < MOUT*D_){ xo[i] = 0.f; qlin[i] = qb[i % D_]; }
    if (i < BH_*NOUT) rowsum[i] = 0.f;
}

// ---------------- rose (rotary) producing bf16 hi/lo directly ----------------
__global__ void rose_hl_kernel(const float* __restrict__ src, int stride, int off,
                               __nv_bfloat16* __restrict__ dh, __nv_bfloat16* __restrict__ dl,
                               int N, int Gw, float sp0, float sp1,
                               const float* __restrict__ fr, const float* __restrict__ temp,
                               int applyTemp){
    int idx = blockIdx.x*blockDim.x + threadIdx.x;
    int total = BH_ * N * HD_;
    if (idx >= total) return;
    int hd = idx & 31;
    int n  = (idx >> 5) % N;
    int bh = idx / (N*32);
    int h = bh % H_, b = bh / H_;
    const float* sp = src + ((size_t)b*N + n)*stride + off + h*HD_;
    float val;
    if (hd < NROT_){
        int m = hd >> 1, s = m >> 2, p = m & 3;
        float coord = (s == 0) ? (float)(n / Gw) * sp0 : (float)(n % Gw) * sp1;
        float ang = coord * fr[(h*2 + s)*4 + p];
        float cs, sn; sincosf(ang, &sn, &cs);
        float x1 = sp[2*m], x2 = sp[2*m+1];
        val = (hd & 1) ? (x1*sn + x2*cs) : (x1*cs - x2*sn);
    } else {
        val = sp[hd];
    }
    if (applyTemp) val *= temp[0];
    __nv_bfloat16 hh, ll; split1(val, hh, ll);
    dh[idx] = hh; dl[idx] = ll;
}
__global__ void vT_hl_kernel(const float* __restrict__ kv, __nv_bfloat16* __restrict__ th,
                             __nv_bfloat16* __restrict__ tl){
    int i = blockIdx.x*blockDim.x + threadIdx.x;
    if (i >= BH_*HD_*NIN) return;
    int n  = i % NIN;
    int d  = (i / NIN) % HD_;
    int bh = i / (NIN*HD_);
    int h = bh % H_, b = bh / H_;
    float v = kv[((size_t)b*NIN + n)*(2*D_) + D_ + h*HD_ + d];
    __nv_bfloat16 hh, ll; split1(v, hh, ll);
    th[i] = hh; tl[i] = ll;
}

// ================= HMMA bf16-split dense GEMM =================
#define ASTR 40

struct Frag { unsigned ah[2][4], al[2][4], bh[4][2], bl[4][2]; };

__device__ __forceinline__ void load_frags(Frag& f, const __nv_bfloat16* Ah, const __nv_bfloat16* Al,
                                           const __nv_bfloat16* Bh, const __nv_bfloat16* Bl,
                                           int wm, int wn, int ks, int g, int c2){
    #pragma unroll
    for (int t = 0; t < 2; t++){
        int rb = (wm*32 + t*16 + g)*ASTR + ks + c2;
        f.ah[t][0] = *(const unsigned*)(Ah + rb);
        f.ah[t][1] = *(const unsigned*)(Ah + rb + 8*ASTR);
        f.ah[t][2] = *(const unsigned*)(Ah + rb + 8);
        f.ah[t][3] = *(const unsigned*)(Ah + rb + 8*ASTR + 8);
        f.al[t][0] = *(const unsigned*)(Al + rb);
        f.al[t][1] = *(const unsigned*)(Al + rb + 8*ASTR);
        f.al[t][2] = *(const unsigned*)(Al + rb + 8);
        f.al[t][3] = *(const unsigned*)(Al + rb + 8*ASTR + 8);
    }
    #pragma unroll
    for (int u = 0; u < 4; u++){
        int nb = (wn*32 + u*8 + g)*ASTR + ks + c2;
        f.bh[u][0] = *(const unsigned*)(Bh + nb);
        f.bh[u][1] = *(const unsigned*)(Bh + nb + 8);
        f.bl[u][0] = *(const unsigned*)(Bl + nb);
        f.bl[u][1] = *(const unsigned*)(Bl + nb + 8);
    }
}
__device__ __forceinline__ void do_mmas(float (*acc)[4], const Frag& f){
    #pragma unroll
    for (int t = 0; t < 2; t++)
        #pragma unroll
        for (int u = 0; u < 4; u++){
            mma16816(acc[t*4+u], f.ah[t], f.bh[u]);
            mma16816(acc[t*4+u], f.ah[t], f.bl[u]);
            mma16816(acc[t*4+u], f.al[t], f.bh[u]);
        }
}
__device__ __forceinline__ void epi(float (*acc)[4], const float* __restrict__ bias,
                                    float* __restrict__ C, int M, int N, int m0, int n0,
                                    int wm, int wn, int g, int c2, int act, int atom){
    #pragma unroll
    for (int t = 0; t < 2; t++){
        int r0 = m0 + wm*32 + t*16 + g;
        #pragma unroll
        for (int u = 0; u < 4; u++){
            int cb = n0 + wn*32 + u*8 + c2;
            float* ac = acc[t*4+u];
            if (atom){
                if (r0 < M){
                    atomicAdd(&C[(size_t)r0*N + cb],     ac[0]);
                    atomicAdd(&C[(size_t)r0*N + cb + 1], ac[1]);
                }
                if (r0 + 8 < M){
                    atomicAdd(&C[(size_t)(r0+8)*N + cb],     ac[2]);
                    atomicAdd(&C[(size_t)(r0+8)*N + cb + 1], ac[3]);
                }
            } else {
                float b0 = bias[cb], b1 = bias[cb+1];
                float o0 = ac[0]+b0, o1 = ac[1]+b1, o2 = ac[2]+b0, o3 = ac[3]+b1;
                if (act){ o0=gelu_f(o0); o1=gelu_f(o1); o2=gelu_f(o2); o3=gelu_f(o3); }
                if (r0 < M){ C[(size_t)r0*N + cb] = o0; C[(size_t)r0*N + cb + 1] = o1; }
                if (r0 + 8 < M){ C[(size_t)(r0+8)*N + cb] = o2; C[(size_t)(r0+8)*N + cb + 1] = o3; }
            }
        }
    }
}
__device__ __forceinline__ void fillA(__nv_bfloat16* Ah, __nv_bfloat16* Al,
                                      const float* __restrict__ A, int M, int K,
                                      int m0, int k0, int tid){
    #pragma unroll
    for (int i = 0; i < 4; i++){
        int e = tid + i*256;
        int row = e >> 3, kg = (e & 7)*4;
        float4 v = (m0+row < M) ? *(const float4*)(A + (size_t)(m0+row)*K + k0 + kg)
                                : make_float4(0.f,0.f,0.f,0.f);
        unsigned h0,h1,l0,l1; split4(v, h0,h1,l0,l1);
        unsigned* ph = (unsigned*)&Ah[row*ASTR + kg];
        unsigned* pl = (unsigned*)&Al[row*ASTR + kg];
        ph[0]=h0; ph[1]=h1; pl[0]=l0; pl[1]=l1;
    }
}
__device__ __forceinline__ void fillB(__nv_bfloat16* Bh, __nv_bfloat16* Bl,
                                      const __nv_bfloat16* __restrict__ Wh,
                                      const __nv_bfloat16* __restrict__ Wl,
                                      size_t rowbase, int Kst, int n0, int tid){
    int n  = tid >> 2;
    int kb = (tid & 3)*8;
    const unsigned* ph = (const unsigned*)Wh + ((rowbase + (size_t)(n0+n)*Kst + kb) >> 1);
    const unsigned* pl = (const unsigned*)Wl + ((rowbase + (size_t)(n0+n)*Kst + kb) >> 1);
    unsigned* sh = (unsigned*)&Bh[n*ASTR + kb];
    unsigned* sl = (unsigned*)&Bl[n*ASTR + kb];
    #pragma unroll
    for (int j = 0; j < 4; j++){ sh[j] = ph[j]; sl[j] = pl[j]; }
}

__global__ __launch_bounds__(256, 2)
void mgemm_kernel(const float* __restrict__ A, const __nv_bfloat16* __restrict__ Wh,
                  const __nv_bfloat16* __restrict__ Wl,
                  const float* __restrict__ bias, float* __restrict__ C,
                  int M, int N, int K, int kSlice, int act, int atom){
    __shared__ __align__(16) __nv_bfloat16 Ah[128*ASTR], Al[128*ASTR];
    __shared__ __align__(16) __nv_bfloat16 Bh[64*ASTR],  Bl[64*ASTR];
    int tid = threadIdx.x, lane = tid & 31, wid = tid >> 5;
    int wm = wid >> 1, wn = wid & 1;
    int g = lane >> 2, c2 = (lane & 3)*2;
    int m0 = blockIdx.y*128, n0 = blockIdx.x*64;
    int kb0 = blockIdx.z*kSlice, kend = kb0 + kSlice;
    float acc[8][4] = {};
    for (int k0 = kb0; k0 < kend; k0 += 32){
        fillA(Ah, Al, A, M, K, m0, k0, tid);
        fillB(Bh, Bl, Wh, Wl, (size_t)k0, K, n0, tid);
        __syncthreads();
        #pragma unroll
        for (int ks = 0; ks < 32; ks += 16){
            Frag f;
            load_frags(f, Ah, Al, Bh, Bl, wm, wn, ks, g, c2);
            do_mmas(acc, f);
        }
        __syncthreads();
    }
    epi(acc, bias, C, M, N, m0, n0, wm, wn, g, c2, act, atom);
}

// A pre-split variant (for kv GEMM on x)
__global__ __launch_bounds__(256, 2)
void mgemm_pre_kernel(const __nv_bfloat16* __restrict__ Xh, const __nv_bfloat16* __restrict__ Xl,
                      const __nv_bfloat16* __restrict__ Wh, const __nv_bfloat16* __restrict__ Wl,
                      const float* __restrict__ bias, float* __restrict__ C,
                      int M, int N, int K){
    __shared__ __align__(16) __nv_bfloat16 Ah[128*ASTR], Al[128*ASTR];
    __shared__ __align__(16) __nv_bfloat16 Bh[64*ASTR],  Bl[64*ASTR];
    int tid = threadIdx.x, lane = tid & 31, wid = tid >> 5;
    int wm = wid >> 1, wn = wid & 1;
    int g = lane >> 2, c2 = (lane & 3)*2;
    int m0 = blockIdx.y*128, n0 = blockIdx.x*64;
    float acc[8][4] = {};
    for (int k0 = 0; k0 < K; k0 += 32){
        #pragma unroll
        for (int i = 0; i < 4; i++){
            int e = tid + i*256;
            int row = e >> 3, kg = (e & 7)*4;
            size_t off = (size_t)(m0+row)*K + k0 + kg;
            uint2 h = make_uint2(0u,0u), l = h;
            if (m0+row < M){
                h = *(const uint2*)(Xh + off);
                l = *(const uint2*)(Xl + off);
            }
            *(uint2*)&Ah[row*ASTR + kg] = h;
            *(uint2*)&Al[row*ASTR + kg] = l;
        }
        fillB(Bh, Bl, Wh, Wl, (size_t)k0, K, n0, tid);
        __syncthreads();
        #pragma unroll
        for (int ks = 0; ks < 32; ks += 16){
            Frag f;
            load_frags(f, Ah, Al, Bh, Bl, wm, wn, ks, g, c2);
            do_mmas(acc, f);
        }
        __syncthreads();
    }
    epi(acc, bias, C, M, N, m0, n0, wm, wn, g, c2, 0, 0);
}

// conv implicit GEMM with pre-split x; grid.z = 7 kh-slices, atomic epilogue
// occupancy 3 -> 444-CTA capacity -> 336-block grid runs in a single wave
__global__ __launch_bounds__(256, 3)
void mconv_kernel(const __nv_bfloat16* __restrict__ Xh, const __nv_bfloat16* __restrict__ Xl,
                  const __nv_bfloat16* __restrict__ Wh, const __nv_bfloat16* __restrict__ Wl,
                  float* __restrict__ C){
    __shared__ __align__(16) __nv_bfloat16 Ah[128*ASTR], Al[128*ASTR];
    __shared__ __align__(16) __nv_bfloat16 Bh[64*ASTR],  Bl[64*ASTR];
    int tid = threadIdx.x, lane = tid & 31, wid = tid >> 5;
    int wm = wid >> 1, wn = wid & 1;
    int g = lane >> 2, c2 = (lane & 3)*2;
    int m0 = blockIdx.y*128, n0 = blockIdx.x*64;
    int slice = blockIdx.z;
    float acc[8][4] = {};
    for (int kc = 0; kc < 7*D_; kc += 32){
        int khw = slice*7 + kc/D_;
        int cib = kc % D_;
        int kh = khw/7, kw = khw%7;
        #pragma unroll
        for (int i = 0; i < 4; i++){
            int e = tid + i*256;
            int row = e >> 3, kg = (e & 7)*4;
            int m = m0 + row;
            uint2 h = make_uint2(0u,0u), l = h;
            if (m < MOUT){
                int bb = m / NOUT, rr = m % NOUT;
                int oh = rr / QG, ow = rr % QG;
                int ih = oh*3 - 3 + kh, iw = ow*3 - 3 + kw;
                if ((unsigned)ih < 64u && (unsigned)iw < 64u){
                    size_t off = ((size_t)(bb*NIN + ih*GW_ + iw))*D_ + cib + kg;
                    h = *(const uint2*)(Xh + off);
                    l = *(const uint2*)(Xl + off);
                }
            }
            *(uint2*)&Ah[row*ASTR + kg] = h;
            *(uint2*)&Al[row*ASTR + kg] = l;
        }
        fillB(Bh, Bl, Wh, Wl, (size_t)(khw*D_ + cib), CKK, n0, tid);
        __syncthreads();
        #pragma unroll
        for (int ks = 0; ks < 32; ks += 16){
            Frag f;
            load_frags(f, Ah, Al, Bh, Bl, wm, wn, ks, g, c2);
            do_mmas(acc, f);
        }
        __syncthreads();
    }
    epi(acc, (const float*)0, C, MOUT, D_, m0, n0, wm, wn, g, c2, 0, 1);
}

// ---------------- one-pass layernorm over D=384, optional residual-add -------------
__global__ void ln_kernel(const float* __restrict__ X, const float* __restrict__ g,
                          const float* __restrict__ bt, float* __restrict__ out, int add){
    int row = blockIdx.x, tid = threadIdx.x;
    float x = X[(size_t)row*D_ + tid];
    __shared__ float w1s[12], w2s[12];
    float s1 = x, s2 = x*x;
    #pragma unroll
    for (int o = 16; o > 0; o >>= 1){
        s1 += __shfl_down_sync(0xffffffffu, s1, o);
        s2 += __shfl_down_sync(0xffffffffu, s2, o);
    }
    if ((tid & 31) == 0){ w1s[tid >> 5] = s1; w2s[tid >> 5] = s2; }
    __syncthreads();
    if (tid == 0){
        float t1 = 0.f, t2 = 0.f;
        #pragma unroll
        for (int i = 0; i < 12; i++){ t1 += w1s[i]; t2 += w2s[i]; }
        w1s[0] = t1; w2s[0] = t2;
    }
    __syncthreads();
    float mu  = w1s[0] * (1.0f/D_);
    float var = w2s[0] * (1.0f/D_) - mu*mu;
    float y = (x - mu) * rsqrtf(var + LNEPS) * g[tid] + bt[tid];
    size_t o_ = (size_t)row*D_ + tid;
    out[o_] = add ? (out[o_] + y) : y;
}

// ======== HMMA scores (hi-only QK): E = exp(Q K^T); store d = E-1 fp16 ========
__global__ __launch_bounds__(256)
void mscore_kernel(const __nv_bfloat16* __restrict__ Qh,
                   const __nv_bfloat16* __restrict__ Kh,
                   __half* __restrict__ Eh, float* __restrict__ rowsum){
    __shared__ __align__(16) __nv_bfloat16 Qhs[64*ASTR];
    __shared__ __align__(16) __nv_bfloat16 Khs[128*ASTR];
    __shared__ float rs[64];
    int tid = threadIdx.x, lane = tid & 31, wid = tid >> 5;
    int wq = wid >> 2, wk = wid & 3;
    int g = lane >> 2, c2 = (lane & 3)*2;
    int kt = blockIdx.x*128, q0 = blockIdx.y*64, bh = blockIdx.z;
    if (tid < 64) rs[tid] = 0.f;
    {
        int row = tid >> 2, kb = (tid & 3)*8;
        unsigned* sh = (unsigned*)&Qhs[row*ASTR + kb];
        if (q0 + row < NOUT){
            size_t e32 = ((size_t)(bh*NOUT + q0 + row)*HD_ + kb) >> 1;
            const unsigned* ph = (const unsigned*)Qh + e32;
            #pragma unroll
            for (int j = 0; j < 4; j++) sh[j] = ph[j];
        } else {
            #pragma unroll
            for (int j = 0; j < 4; j++) sh[j] = 0u;
        }
    }
    {
        int row = tid >> 1, kb = (tid & 1)*16;
        size_t e32 = ((size_t)(bh*NIN + kt + row)*HD_ + kb) >> 1;
        const unsigned* ph = (const unsigned*)Kh + e32;
        unsigned* sh = (unsigned*)&Khs[row*ASTR + kb];
        #pragma unroll
        for (int j = 0; j < 8; j++) sh[j] = ph[j];
    }
    __syncthreads();
    float acc[2][4][4] = {};
    #pragma unroll
    for (int ks = 0; ks < 32; ks += 16){
        unsigned ah[2][4], bhf[4][2];
        #pragma unroll
        for (int t = 0; t < 2; t++){
            int rb = (wq*32 + t*16 + g)*ASTR + ks + c2;
            ah[t][0] = *(const unsigned*)(Qhs + rb);
            ah[t][1] = *(const unsigned*)(Qhs + rb + 8*ASTR);
            ah[t][2] = *(const unsigned*)(Qhs + rb + 8);
            ah[t][3] = *(const unsigned*)(Qhs + rb + 8*ASTR + 8);
        }
        #pragma unroll
        for (int u = 0; u < 4; u++){
            int nb = (wk*32 + u*8 + g)*ASTR + ks + c2;
            bhf[u][0] = *(const unsigned*)(Khs + nb);
            bhf[u][1] = *(const unsigned*)(Khs + nb + 8);
        }
        #pragma unroll
        for (int t = 0; t < 2; t++)
            #pragma unroll
            for (int u = 0; u < 4; u++)
                mma16816(acc[t][u], ah[t], bhf[u]);
    }
    #pragma unroll
    for (int t = 0; t < 2; t++){
        int lr = wq*32 + t*16 + g;
        int r  = q0 + lr;
        float s0 = 0.f, s1 = 0.f;
        #pragma unroll
        for (int u = 0; u < 4; u++){
            int col = kt + wk*32 + u*8 + c2;
            float e0 = exp_fast(acc[t][u][0]), e1 = exp_fast(acc[t][u][1]);
            float e2 = exp_fast(acc[t][u][2]), e3 = exp_fast(acc[t][u][3]);
            __half2 v0 = __floats2half2_rn(e0 - 1.0f, e1 - 1.0f);
            __half2 v1 = __floats2half2_rn(e2 - 1.0f, e3 - 1.0f);
            if (r < NOUT)
                *(__half2*)(Eh + (size_t)(bh*NOUT + r)*NIN + col) = v0;
            if (r + 8 < NOUT)
                *(__half2*)(Eh + (size_t)(bh*NOUT + r + 8)*NIN + col) = v1;
            s0 += e0 + e1; s1 += e2 + e3;
        }
        s0 += __shfl_xor_sync(0xffffffffu, s0, 1);
        s0 += __shfl_xor_sync(0xffffffffu, s0, 2);
        s1 += __shfl_xor_sync(0xffffffffu, s1, 1);
        s1 += __shfl_xor_sync(0xffffffffu, s1, 2);
        if ((lane & 3) == 0){
            atomicAdd(&rs[lr], s0);
            atomicAdd(&rs[lr + 8], s1);
        }
    }
    __syncthreads();
    if (tid < 64 && q0 + tid < NOUT)
        atomicAdd(rowsum + bh*NOUT + q0 + tid, rs[tid]);
}

__global__ void rowinv_kernel(float* __restrict__ rowsum){
    int i = blockIdx.x*blockDim.x + threadIdx.x;
    if (i < BH_*NOUT) rowsum[i] = 1.f / rowsum[i];
}

__global__ void colsum_kernel(const __half* __restrict__ Eh, const float* __restrict__ rinv,
                              float* __restrict__ colinv){
    int bh = blockIdx.y;
    int col = blockIdx.x*256 + threadIdx.x;
    const __half* a = Eh + (size_t)bh*NOUT*NIN + col;
    const float* ri = rinv + bh*NOUT;
    float s = 0.f;
    #pragma unroll 4
    for (int qi = 0; qi < NOUT; qi++)
        s += (1.0f + __half2float(a[(size_t)qi*NIN])) * __ldg(ri + qi);
    colinv[bh*NIN + col] = 1.f / (s + EPSV);
}

// ======== HMMA PV: upd += (E*rinv*colinv) @ V, split-K=4, atomic epilogue ========
// writeout: also emit attn_k = E*rinv and attn_q = E*rinv*colinv (fp32) on last iter.
#define PSTR 72
__global__ __launch_bounds__(256)
void mpv_kernel(const __half* __restrict__ Eh,
                const float* __restrict__ rinv, const float* __restrict__ colinv,
                const __nv_bfloat16* __restrict__ Vth, const __nv_bfloat16* __restrict__ Vtl,
                float* __restrict__ out, float* __restrict__ outk, float* __restrict__ outq,
                int writeout){
    __shared__ __align__(16) __nv_bfloat16 Ahs[64*PSTR], Als[64*PSTR];
    __shared__ __align__(16) __nv_bfloat16 Vhs[32*PSTR], Vls[32*PSTR];
    int tid = threadIdx.x, lane = tid & 31, wid = tid >> 5;
    int wq = wid >> 1, wd = wid & 1;
    int g = lane >> 2, c2 = (lane & 3)*2;
    int q0 = blockIdx.x*64, bh = blockIdx.y;
    int ks0 = blockIdx.z*1024;
    float acc[2][4] = {};
    int frow = tid >> 4, fcol = (tid & 15)*4;
    float rv[4];
    #pragma unroll
    for (int i = 0; i < 4; i++){
        int r = q0 + frow + i*16;
        rv[i] = (r < NOUT) ? rinv[bh*NOUT + r] : 0.f;
    }
    for (int c = 0; c < 16; c++){
        int k0 = ks0 + c*64;
        #pragma unroll
        for (int i = 0; i < 4; i++){
            int row = frow + i*16;
            int r = q0 + row;
            float4 e = make_float4(0.f,0.f,0.f,0.f);
            size_t base = (size_t)(bh*NOUT + (r < NOUT ? r : 0))*NIN + k0 + fcol;
            if (r < NOUT){
                uint2 u = *(const uint2*)(Eh + base);
                float2 f0 = __half22float2(*(__half2*)&u.x);
                float2 f1 = __half22float2(*(__half2*)&u.y);
                e = make_float4(1.0f + f0.x, 1.0f + f0.y, 1.0f + f1.x, 1.0f + f1.y);
            }
            float4 cv = *(const float4*)(colinv + bh*NIN + k0 + fcol);
            float4 a;
            a.x = e.x*rv[i]*cv.x; a.y = e.y*rv[i]*cv.y;
            a.z = e.z*rv[i]*cv.z; a.w = e.w*rv[i]*cv.w;
            if (writeout && r < NOUT){
                float4 ak;
                ak.x = e.x*rv[i]; ak.y = e.y*rv[i];
                ak.z = e.z*rv[i]; ak.w = e.w*rv[i];
                *(float4*)(outk + base) = ak;
                *(float4*)(outq + base) = a;
            }
            unsigned h0,h1,l0,l1; split4(a, h0,h1,l0,l1);
            unsigned* ph = (unsigned*)&Ahs[row*PSTR + fcol];
            unsigned* pl = (unsigned*)&Als[row*PSTR + fcol];
            ph[0]=h0; ph[1]=h1; pl[0]=l0; pl[1]=l1;
        }
        {
            int d = tid >> 3, kb = (tid & 7)*8;
            size_t e32 = ((size_t)(bh*HD_ + d)*NIN + k0 + kb) >> 1;
            const unsigned* ph = (const unsigned*)Vth + e32;
            const unsigned* pl = (const unsigned*)Vtl + e32;
            unsigned* sh = (unsigned*)&Vhs[d*PSTR + kb];
            unsigned* sl = (unsigned*)&Vls[d*PSTR + kb];
            #pragma unroll
            for (int j = 0; j < 4; j++){ sh[j] = ph[j]; sl[j] = pl[j]; }
        }
        __syncthreads();
        #pragma unroll
        for (int ks = 0; ks < 64; ks += 16){
            unsigned a_h[4], a_l[4];
            int rb = (wq*16 + g)*PSTR + ks + c2;
            a_h[0] = *(const unsigned*)(Ahs + rb);
            a_h[1] = *(const unsigned*)(Ahs + rb + 8*PSTR);
            a_h[2] = *(const unsigned*)(Ahs + rb + 8);
            a_h[3] = *(const unsigned*)(Ahs + rb + 8*PSTR + 8);
            a_l[0] = *(const unsigned*)(Als + rb);
            a_l[1] = *(const unsigned*)(Als + rb + 8*PSTR);
            a_l[2] = *(const unsigned*)(Als + rb + 8);
            a_l[3] = *(const unsigned*)(Als + rb + 8*PSTR + 8);
            #pragma unroll
            for (int u = 0; u < 2; u++){
                unsigned b_h[2], b_l[2];
                int nb = (wd*16 + u*8 + g)*PSTR + ks + c2;
                b_h[0] = *(const unsigned*)(Vhs + nb);
                b_h[1] = *(const unsigned*)(Vhs + nb + 8);
                b_l[0] = *(const unsigned*)(Vls + nb);
                b_l[1] = *(const unsigned*)(Vls + nb + 8);
                mma16816(acc[u], a_h, b_h);
                mma16816(acc[u], a_h, b_l);
                mma16816(acc[u], a_l, b_h);
            }
        }
        __syncthreads();
    }
    int b = bh / H_, h = bh % H_;
    int r0 = q0 + wq*16 + g;
    #pragma unroll
    for (int u = 0; u < 2; u++){
        int col = h*HD_ + wd*16 + u*8 + c2;
        if (r0 < NOUT){
            atomicAdd(out + (size_t)(b*NOUT + r0)*D_ + col,     acc[u][0]);
            atomicAdd(out + (size_t)(b*NOUT + r0)*D_ + col + 1, acc[u][1]);
        }
        if (r0 + 8 < NOUT){
            atomicAdd(out + (size_t)(b*NOUT + r0 + 8)*D_ + col,     acc[u][2]);
            atomicAdd(out + (size_t)(b*NOUT + r0 + 8)*D_ + col + 1, acc[u][3]);
        }
    }
}

// ---------------- host orchestration ----------------------------------------------
extern "C" void kernel_launch(void* const* d_in, const int* in_sizes, int n_in,
                              void* d_out, int out_size){
    const float* x      = (const float*)d_in[0];
    const float* conv_w = (const float*)d_in[1];
    const float* conv_b = (const float*)d_in[2];
    const float* kv_w   = (const float*)d_in[3];
    const float* kv_b   = (const float*)d_in[4];
    const float* q_w    = (const float*)d_in[5];
    const float* q_b    = (const float*)d_in[6];
    const float* w1     = (const float*)d_in[7];
    const float* b1m    = (const float*)d_in[8];
    const float* w2     = (const float*)d_in[9];
    const float* b2m    = (const float*)d_in[10];
    const float* g1     = (const float*)d_in[11];
    const float* b1_    = (const float*)d_in[12];
    const float* g2     = (const float*)d_in[13];
    const float* b2_    = (const float*)d_in[14];
    const float* g3     = (const float*)d_in[15];
    const float* b3_    = (const float*)d_in[16];
    const float* temp   = (const float*)d_in[17];
    const float* freqs  = (const float*)d_in[18];

    __nv_bfloat16 *cwh,*cwl,*kvwh,*kvwl,*qwh,*qwl,*w1h,*w1l,*w2h,*w2l;
    __nv_bfloat16 *xh,*xl,*kh,*kl,*vth,*vtl,*qh,*ql;
    float *xo,*xoutg,*kv,*qlin,*attn_s,*rowsum,*colinv,*h1;
    cudaGetSymbolAddress((void**)&cwh,  g_cwh);  cudaGetSymbolAddress((void**)&cwl,  g_cwl);
    cudaGetSymbolAddress((void**)&kvwh, g_kvwh); cudaGetSymbolAddress((void**)&kvwl, g_kvwl);
    cudaGetSymbolAddress((void**)&qwh,  g_qwh);  cudaGetSymbolAddress((void**)&qwl,  g_qwl);
    cudaGetSymbolAddress((void**)&w1h,  g_w1h);  cudaGetSymbolAddress((void**)&w1l,  g_w1l);
    cudaGetSymbolAddress((void**)&w2h,  g_w2h);  cudaGetSymbolAddress((void**)&w2l,  g_w2l);
    cudaGetSymbolAddress((void**)&xh,   g_xh);   cudaGetSymbolAddress((void**)&xl,   g_xl);
    cudaGetSymbolAddress((void**)&kh,   g_kh);   cudaGetSymbolAddress((void**)&kl,   g_kl);
    cudaGetSymbolAddress((void**)&vth,  g_vth);  cudaGetSymbolAddress((void**)&vtl,  g_vtl);
    cudaGetSymbolAddress((void**)&qh,   g_qh);   cudaGetSymbolAddress((void**)&ql,   g_ql);
    cudaGetSymbolAddress((void**)&xo,     g_xo);
    cudaGetSymbolAddress((void**)&xoutg,  g_xout);
    cudaGetSymbolAddress((void**)&kv,     g_kv);
    cudaGetSymbolAddress((void**)&qlin,   g_qlin);
    cudaGetSymbolAddress((void**)&attn_s, g_attn);
    cudaGetSymbolAddress((void**)&rowsum, g_rowsum);
    cudaGetSymbolAddress((void**)&colinv, g_colinv);
    cudaGetSymbolAddress((void**)&h1,     g_h1);

    float* out = (float*)d_out;
    bool full = (size_t)out_size >= (size_t)XOUT_SZ + 2*ATTN_SZ;
    float* xout      = full ? out : xoutg;                       // x_out in place
    float* out_attnq = full ? out + XOUT_SZ : attn_s;
    float* out_attnk = full ? out + XOUT_SZ + ATTN_SZ : attn_s;
    __half* Eh       = (__half*)attn_s;                          // fp16 (E-1), all iters

    // ---- prologue: pack weights + pre-split x ----
    packconvT_kernel<<<(D_*CKK + 255)/256, 256>>>(conv_w, cwh, cwl);
    packT_kernel<<<(D_*2*D_ + 255)/256, 256>>>(kv_w, kvwh, kvwl, D_, 2*D_);
    packT_kernel<<<(D_*D_ + 255)/256, 256>>>(q_w, qwh, qwl, D_, D_);
    packT_kernel<<<(D_*4*D_ + 255)/256, 256>>>(w1, w1h, w1l, D_, 4*D_);
    packT_kernel<<<(4*D_*D_ + 255)/256, 256>>>(w2, w2h, w2l, 4*D_, D_);
    splitf_kernel<<<(MIN_*D_ + 255)/256, 256>>>(x, xh, xl, MIN_*D_);

    // ---- conv + first LN ----
    seed_kernel<<<(MOUT*D_ + 255)/256, 256>>>(conv_b, xo, MOUT, D_);
    mconv_kernel<<<dim3(D_/64, (MOUT+127)/128, 7), 256>>>(xh, xl, cwh, cwl, xo);
    ln_kernel<<<MOUT, D_>>>(xo, g1, b1_, xout, 0);

    // ---- kv (loop-invariant) + rose-split ----
    mgemm_pre_kernel<<<dim3(2*D_/64, MIN_/128), 256>>>(xh, xl, kvwh, kvwl, kv_b, kv, MIN_, 2*D_, D_);
    int totk = BH_*NIN*HD_;
    rose_hl_kernel<<<(totk+255)/256, 256>>>(kv, 2*D_, 0, kh, kl, NIN, GW_, 1.f, 1.f, freqs, temp, 1);
    vT_hl_kernel<<<(totk+255)/256, 256>>>(kv, vth, vtl);

    int totq = BH_*NOUT*HD_;
    for (int it = 0; it < 3; it++){
        int writeout = (it == 2 && full) ? 1 : 0;
        prep_kernel<<<(MOUT*D_ + 255)/256, 256>>>(q_b, qlin, xo, rowsum);
        mgemm_kernel<<<dim3(D_/64, (MOUT+127)/128, 2), 256>>>(xout, qwh, qwl, q_b, qlin, MOUT, D_, D_, D_/2, 0, 1);
        rose_hl_kernel<<<(totq+255)/256, 256>>>(qlin, D_, 0, qh, ql, NOUT, QG, 3.f, 3.f, freqs, temp, 0);

        mscore_kernel<<<dim3(NIN/128, (NOUT+63)/64, BH_), 256>>>(qh, kh, Eh, rowsum);
        rowinv_kernel<<<(BH_*NOUT + 255)/256, 256>>>(rowsum);
        colsum_kernel<<<dim3(NIN/256, BH_), 256>>>(Eh, rowsum, colinv);
        mpv_kernel<<<dim3((NOUT+63)/64, BH_, 4), 256>>>(Eh, rowsum, colinv, vth, vtl,
                                                        xo, out_attnk, out_attnq, writeout);
        ln_kernel<<<MOUT, D_>>>(xo, g2, b2_, xout, 1);

        mgemm_kernel<<<dim3(4*D_/64, (MOUT+127)/128, 1), 256>>>(xout, w1h, w1l, b1m, h1, MOUT, 4*D_, D_, D_, 1, 0);
        seed_kernel<<<(MOUT*D_ + 255)/256, 256>>>(b2m, xo, MOUT, D_);
        mgemm_kernel<<<dim3(D_/64, (MOUT+127)/128, 2), 256>>>(h1, w2h, w2l, b2m, xo, MOUT, D_, 4*D_, 2*D_, 0, 1);
        ln_kernel<<<MOUT, D_>>>(xo, g3, b3_, xout, 1);
    }
}

// round 16
// speedup vs baseline: 1.2124x; 1.0114x over previous
#include <cuda_runtime.h>
#include <cuda_bf16.h>
#include <cuda_fp16.h>
#include <math.h>
#include <stdint.h>

// ---------------- problem constants ----------------
#define B_    2
#define NIN   4096
#define NOUT  484
#define D_    384
#define H_    12
#define HD_   32
#define QG    22
#define GW_   64
#define MOUT  (B_*NOUT)   // 968
#define MIN_  (B_*NIN)    // 8192
#define BH_   (B_*H_)     // 24
#define NROT_ 16
#define LNEPS 1e-5f
#define EPSV  1.1920929e-07f
#define CKK   (49*D_)     // 18816 conv k-extent

#define XOUT_SZ  (MOUT*D_)                       // 371712
#define ATTN_SZ  ((size_t)BH_*NOUT*NIN)          // 47579136

// ---------------- scratch (device globals; no alloc allowed) ----------------
__device__ __nv_bfloat16 g_cwh[D_*CKK],  g_cwl[D_*CKK];       // conv w: [co][khw*384+ci]
__device__ __nv_bfloat16 g_kvwh[2*D_*D_], g_kvwl[2*D_*D_];
__device__ __nv_bfloat16 g_qwh[D_*D_],    g_qwl[D_*D_];
__device__ __nv_bfloat16 g_w1h[4*D_*D_],  g_w1l[4*D_*D_];
__device__ __nv_bfloat16 g_w2h[D_*4*D_],  g_w2l[D_*4*D_];
__device__ __nv_bfloat16 g_xh[MIN_*D_],   g_xl[MIN_*D_];       // pre-split input x
__device__ __nv_bfloat16 g_kh[BH_*NIN*HD_],  g_kl[BH_*NIN*HD_];
__device__ __nv_bfloat16 g_vth[BH_*HD_*NIN], g_vtl[BH_*HD_*NIN];  // [bh][d][n]
__device__ __nv_bfloat16 g_qh[BH_*NOUT*HD_], g_ql[BH_*NOUT*HD_];
__device__ float g_xo[MOUT*D_];
__device__ float g_xout[MOUT*D_];                 // fallback only
__device__ float g_kv[MIN_*2*D_];
__device__ float g_qlin[MOUT*D_];
__device__ float g_attn[(size_t)BH_*NOUT*NIN];    // fp16 (E-1) store + fallback region
__device__ float g_rowsum[BH_*NOUT];
__device__ float g_colinv[BH_*NIN];
__device__ float g_h1[MOUT*4*D_];

// ---------------- helpers ----------------
__device__ __forceinline__ float gelu_f(float x){
    return 0.5f * x * (1.0f + erff(x * 0.70710678118654752f));
}
__device__ __forceinline__ void split1(float v, __nv_bfloat16& h, __nv_bfloat16& l){
    h = __float2bfloat16(v);
    l = __float2bfloat16(v - __bfloat162float(h));
}
__device__ __forceinline__ void split4(float4 v, unsigned& h0, unsigned& h1,
                                       unsigned& l0, unsigned& l1){
    __nv_bfloat162 hx = __floats2bfloat162_rn(v.x, v.y);
    __nv_bfloat162 hz = __floats2bfloat162_rn(v.z, v.w);
    float2 fx = __bfloat1622float2(hx);
    float2 fz = __bfloat1622float2(hz);
    __nv_bfloat162 lx = __floats2bfloat162_rn(v.x - fx.x, v.y - fx.y);
    __nv_bfloat162 lz = __floats2bfloat162_rn(v.z - fz.x, v.w - fz.y);
    h0 = *(unsigned*)&hx; h1 = *(unsigned*)&hz;
    l0 = *(unsigned*)&lx; l1 = *(unsigned*)&lz;
}
// FFMA-only exp (no MUFU), rel err ~1.2e-7
__device__ __forceinline__ float exp_fast(float x){
    float t = x * 1.4426950408889634f;
    float r = t + 12582912.0f;
    int   n = __float_as_int(r) - 0x4B400000;
    float f = t - (r - 12582912.0f);
    float p =            1.5403530e-4f;
    p = fmaf(p, f, 1.3333558e-3f);
    p = fmaf(p, f, 9.6181291e-3f);
    p = fmaf(p, f, 5.5504109e-2f);
    p = fmaf(p, f, 2.4022651e-1f);
    p = fmaf(p, f, 6.9314718e-1f);
    p = fmaf(p, f, 1.0f);
    return __int_as_float(__float_as_int(p) + (n << 23));
}
__device__ __forceinline__ void mma16816(float* c, const unsigned* a, const unsigned* b){
    asm volatile("mma.sync.aligned.m16n8k16.row.col.f32.bf16.bf16.f32 "
        "{%0,%1,%2,%3},{%4,%5,%6,%7},{%8,%9},{%0,%1,%2,%3};"
        : "+f"(c[0]), "+f"(c[1]), "+f"(c[2]), "+f"(c[3])
        : "r"(a[0]), "r"(a[1]), "r"(a[2]), "r"(a[3]), "r"(b[0]), "r"(b[1]));
}

// ---------------- prologue pack kernels ----------------
__global__ void packT_kernel(const float* __restrict__ src, __nv_bfloat16* __restrict__ h,
                             __nv_bfloat16* __restrict__ l, int K, int N){
    int idx = blockIdx.x*blockDim.x + threadIdx.x;
    if (idx >= K*N) return;
    int n = idx / K, k = idx % K;
    __nv_bfloat16 hh, ll; split1(src[(size_t)k*N + n], hh, ll);
    h[idx] = hh; l[idx] = ll;
}
// conv weights: per-co smem transpose. src [co][ci][khw] -> dst [co][khw*384+ci]
__global__ void packconvT_kernel(const float* __restrict__ w, __nv_bfloat16* __restrict__ h,
                                 __nv_bfloat16* __restrict__ l){
    __shared__ float s[64*49];
    int co = blockIdx.x, tid = threadIdx.x;
    for (int cb = 0; cb < 6; cb++){
        for (int i = tid; i < 64*49; i += 256)
            s[i] = w[(size_t)co*CKK + cb*64*49 + i];
        __syncthreads();
        for (int j = tid; j < 49*64; j += 256){
            int khw = j >> 6, ci64 = j & 63;
            __nv_bfloat16 hh, ll; split1(s[ci64*49 + khw], hh, ll);
            size_t o = (size_t)co*CKK + khw*D_ + cb*64 + ci64;
            h[o] = hh; l[o] = ll;
        }
        __syncthreads();
    }
}
__global__ void splitf_kernel(const float* __restrict__ src, __nv_bfloat16* __restrict__ h,
                              __nv_bfloat16* __restrict__ l, int n){
    int i = blockIdx.x*blockDim.x + threadIdx.x;
    if (i >= n) return;
    __nv_bfloat16 hh, ll; split1(src[i], hh, ll);
    h[i] = hh; l[i] = ll;
}
__global__ void seed_kernel(const float* __restrict__ b, float* __restrict__ o, int M, int N){
    int idx = blockIdx.x*blockDim.x + threadIdx.x;
    if (idx < M*N) o[idx] = b[idx % N];
}
// per-iter prep: xo=0, qlin=q_b, rowsum=0
__global__ void prep_kernel(const float* __restrict__ qb, float* __restrict__ qlin,
                            float* __restrict__ xo, float* __restrict__ rowsum){
    int i = blockIdx.x*blockDim.x + threadIdx.x;
    if (i < MOUT*D_){ xo[i] = 0.f; qlin[i] = qb[i % D_]; }
    if (i < BH_*NOUT) rowsum[i] = 0.f;
}

// ---------------- rose (rotary) producing bf16 hi/lo directly ----------------
__global__ void rose_hl_kernel(const float* __restrict__ src, int stride, int off,
                               __nv_bfloat16* __restrict__ dh, __nv_bfloat16* __restrict__ dl,
                               int N, int Gw, float sp0, float sp1,
                               const float* __restrict__ fr, const float* __restrict__ temp,
                               int applyTemp){
    int idx = blockIdx.x*blockDim.x + threadIdx.x;
    int total = BH_ * N * HD_;
    if (idx >= total) return;
    int hd = idx & 31;
    int n  = (idx >> 5) % N;
    int bh = idx / (N*32);
    int h = bh % H_, b = bh / H_;
    const float* sp = src + ((size_t)b*N + n)*stride + off + h*HD_;
    float val;
    if (hd < NROT_){
        int m = hd >> 1, s = m >> 2, p = m & 3;
        float coord = (s == 0) ? (float)(n / Gw) * sp0 : (float)(n % Gw) * sp1;
        float ang = coord * fr[(h*2 + s)*4 + p];
        float cs, sn; sincosf(ang, &sn, &cs);
        float x1 = sp[2*m], x2 = sp[2*m+1];
        val = (hd & 1) ? (x1*sn + x2*cs) : (x1*cs - x2*sn);
    } else {
        val = sp[hd];
    }
    if (applyTemp) val *= temp[0];
    __nv_bfloat16 hh, ll; split1(val, hh, ll);
    dh[idx] = hh; dl[idx] = ll;
}
__global__ void vT_hl_kernel(const float* __restrict__ kv, __nv_bfloat16* __restrict__ th,
                             __nv_bfloat16* __restrict__ tl){
    int i = blockIdx.x*blockDim.x + threadIdx.x;
    if (i >= BH_*HD_*NIN) return;
    int n  = i % NIN;
    int d  = (i / NIN) % HD_;
    int bh = i / (NIN*HD_);
    int h = bh % H_, b = bh / H_;
    float v = kv[((size_t)b*NIN + n)*(2*D_) + D_ + h*HD_ + d];
    __nv_bfloat16 hh, ll; split1(v, hh, ll);
    th[i] = hh; tl[i] = ll;
}

// ================= HMMA bf16-split dense GEMM =================
#define ASTR 40

struct Frag { unsigned ah[2][4], al[2][4], bh[4][2], bl[4][2]; };

__device__ __forceinline__ void load_frags(Frag& f, const __nv_bfloat16* Ah, const __nv_bfloat16* Al,
                                           const __nv_bfloat16* Bh, const __nv_bfloat16* Bl,
                                           int wm, int wn, int ks, int g, int c2){
    #pragma unroll
    for (int t = 0; t < 2; t++){
        int rb = (wm*32 + t*16 + g)*ASTR + ks + c2;
        f.ah[t][0] = *(const unsigned*)(Ah + rb);
        f.ah[t][1] = *(const unsigned*)(Ah + rb + 8*ASTR);
        f.ah[t][2] = *(const unsigned*)(Ah + rb + 8);
        f.ah[t][3] = *(const unsigned*)(Ah + rb + 8*ASTR + 8);
        f.al[t][0] = *(const unsigned*)(Al + rb);
        f.al[t][1] = *(const unsigned*)(Al + rb + 8*ASTR);
        f.al[t][2] = *(const unsigned*)(Al + rb + 8);
        f.al[t][3] = *(const unsigned*)(Al + rb + 8*ASTR + 8);
    }
    #pragma unroll
    for (int u = 0; u < 4; u++){
        int nb = (wn*32 + u*8 + g)*ASTR + ks + c2;
        f.bh[u][0] = *(const unsigned*)(Bh + nb);
        f.bh[u][1] = *(const unsigned*)(Bh + nb + 8);
        f.bl[u][0] = *(const unsigned*)(Bl + nb);
        f.bl[u][1] = *(const unsigned*)(Bl + nb + 8);
    }
}
__device__ __forceinline__ void do_mmas(float (*acc)[4], const Frag& f){
    #pragma unroll
    for (int t = 0; t < 2; t++)
        #pragma unroll
        for (int u = 0; u < 4; u++){
            mma16816(acc[t*4+u], f.ah[t], f.bh[u]);
            mma16816(acc[t*4+u], f.ah[t], f.bl[u]);
            mma16816(acc[t*4+u], f.al[t], f.bh[u]);
        }
}
__device__ __forceinline__ void epi(float (*acc)[4], const float* __restrict__ bias,
                                    float* __restrict__ C, int M, int N, int m0, int n0,
                                    int wm, int wn, int g, int c2, int act, int atom){
    #pragma unroll
    for (int t = 0; t < 2; t++){
        int r0 = m0 + wm*32 + t*16 + g;
        #pragma unroll
        for (int u = 0; u < 4; u++){
            int cb = n0 + wn*32 + u*8 + c2;
            float* ac = acc[t*4+u];
            if (atom){
                if (r0 < M){
                    atomicAdd(&C[(size_t)r0*N + cb],     ac[0]);
                    atomicAdd(&C[(size_t)r0*N + cb + 1], ac[1]);
                }
                if (r0 + 8 < M){
                    atomicAdd(&C[(size_t)(r0+8)*N + cb],     ac[2]);
                    atomicAdd(&C[(size_t)(r0+8)*N + cb + 1], ac[3]);
                }
            } else {
                float b0 = bias[cb], b1 = bias[cb+1];
                float o0 = ac[0]+b0, o1 = ac[1]+b1, o2 = ac[2]+b0, o3 = ac[3]+b1;
                if (act){ o0=gelu_f(o0); o1=gelu_f(o1); o2=gelu_f(o2); o3=gelu_f(o3); }
                if (r0 < M){ C[(size_t)r0*N + cb] = o0; C[(size_t)r0*N + cb + 1] = o1; }
                if (r0 + 8 < M){ C[(size_t)(r0+8)*N + cb] = o2; C[(size_t)(r0+8)*N + cb + 1] = o3; }
            }
        }
    }
}
__device__ __forceinline__ void fillA(__nv_bfloat16* Ah, __nv_bfloat16* Al,
                                      const float* __restrict__ A, int M, int K,
                                      int m0, int k0, int tid){
    #pragma unroll
    for (int i = 0; i < 4; i++){
        int e = tid + i*256;
        int row = e >> 3, kg = (e & 7)*4;
        float4 v = (m0+row < M) ? *(const float4*)(A + (size_t)(m0+row)*K + k0 + kg)
                                : make_float4(0.f,0.f,0.f,0.f);
        unsigned h0,h1,l0,l1; split4(v, h0,h1,l0,l1);
        unsigned* ph = (unsigned*)&Ah[row*ASTR + kg];
        unsigned* pl = (unsigned*)&Al[row*ASTR + kg];
        ph[0]=h0; ph[1]=h1; pl[0]=l0; pl[1]=l1;
    }
}
__device__ __forceinline__ void fillB(__nv_bfloat16* Bh, __nv_bfloat16* Bl,
                                      const __nv_bfloat16* __restrict__ Wh,
                                      const __nv_bfloat16* __restrict__ Wl,
                                      size_t rowbase, int Kst, int n0, int tid){
    int n  = tid >> 2;
    int kb = (tid & 3)*8;
    const unsigned* ph = (const unsigned*)Wh + ((rowbase + (size_t)(n0+n)*Kst + kb) >> 1);
    const unsigned* pl = (const unsigned*)Wl + ((rowbase + (size_t)(n0+n)*Kst + kb) >> 1);
    unsigned* sh = (unsigned*)&Bh[n*ASTR + kb];
    unsigned* sl = (unsigned*)&Bl[n*ASTR + kb];
    #pragma unroll
    for (int j = 0; j < 4; j++){ sh[j] = ph[j]; sl[j] = pl[j]; }
}

__global__ __launch_bounds__(256, 2)
void mgemm_kernel(const float* __restrict__ A, const __nv_bfloat16* __restrict__ Wh,
                  const __nv_bfloat16* __restrict__ Wl,
                  const float* __restrict__ bias, float* __restrict__ C,
                  int M, int N, int K, int kSlice, int act, int atom){
    __shared__ __align__(16) __nv_bfloat16 Ah[128*ASTR], Al[128*ASTR];
    __shared__ __align__(16) __nv_bfloat16 Bh[64*ASTR],  Bl[64*ASTR];
    int tid = threadIdx.x, lane = tid & 31, wid = tid >> 5;
    int wm = wid >> 1, wn = wid & 1;
    int g = lane >> 2, c2 = (lane & 3)*2;
    int m0 = blockIdx.y*128, n0 = blockIdx.x*64;
    int kb0 = blockIdx.z*kSlice, kend = kb0 + kSlice;
    float acc[8][4] = {};
    for (int k0 = kb0; k0 < kend; k0 += 32){
        fillA(Ah, Al, A, M, K, m0, k0, tid);
        fillB(Bh, Bl, Wh, Wl, (size_t)k0, K, n0, tid);
        __syncthreads();
        #pragma unroll
        for (int ks = 0; ks < 32; ks += 16){
            Frag f;
            load_frags(f, Ah, Al, Bh, Bl, wm, wn, ks, g, c2);
            do_mmas(acc, f);
        }
        __syncthreads();
    }
    epi(acc, bias, C, M, N, m0, n0, wm, wn, g, c2, act, atom);
}

// A pre-split variant (for kv GEMM on x)
__global__ __launch_bounds__(256, 2)
void mgemm_pre_kernel(const __nv_bfloat16* __restrict__ Xh, const __nv_bfloat16* __restrict__ Xl,
                      const __nv_bfloat16* __restrict__ Wh, const __nv_bfloat16* __restrict__ Wl,
                      const float* __restrict__ bias, float* __restrict__ C,
                      int M, int N, int K){
    __shared__ __align__(16) __nv_bfloat16 Ah[128*ASTR], Al[128*ASTR];
    __shared__ __align__(16) __nv_bfloat16 Bh[64*ASTR],  Bl[64*ASTR];
    int tid = threadIdx.x, lane = tid & 31, wid = tid >> 5;
    int wm = wid >> 1, wn = wid & 1;
    int g = lane >> 2, c2 = (lane & 3)*2;
    int m0 = blockIdx.y*128, n0 = blockIdx.x*64;
    float acc[8][4] = {};
    for (int k0 = 0; k0 < K; k0 += 32){
        #pragma unroll
        for (int i = 0; i < 4; i++){
            int e = tid + i*256;
            int row = e >> 3, kg = (e & 7)*4;
            size_t off = (size_t)(m0+row)*K + k0 + kg;
            uint2 h = make_uint2(0u,0u), l = h;
            if (m0+row < M){
                h = *(const uint2*)(Xh + off);
                l = *(const uint2*)(Xl + off);
            }
            *(uint2*)&Ah[row*ASTR + kg] = h;
            *(uint2*)&Al[row*ASTR + kg] = l;
        }
        fillB(Bh, Bl, Wh, Wl, (size_t)k0, K, n0, tid);
        __syncthreads();
        #pragma unroll
        for (int ks = 0; ks < 32; ks += 16){
            Frag f;
            load_frags(f, Ah, Al, Bh, Bl, wm, wn, ks, g, c2);
            do_mmas(acc, f);
        }
        __syncthreads();
    }
    epi(acc, bias, C, M, N, m0, n0, wm, wn, g, c2, 0, 0);
}

// conv implicit GEMM with pre-split x; grid.z = 7 kh-slices, atomic epilogue
// occupancy 3 -> 444-CTA capacity -> 336-block grid runs in a single wave
__global__ __launch_bounds__(256, 3)
void mconv_kernel(const __nv_bfloat16* __restrict__ Xh, const __nv_bfloat16* __restrict__ Xl,
                  const __nv_bfloat16* __restrict__ Wh, const __nv_bfloat16* __restrict__ Wl,
                  float* __restrict__ C){
    __shared__ __align__(16) __nv_bfloat16 Ah[128*ASTR], Al[128*ASTR];
    __shared__ __align__(16) __nv_bfloat16 Bh[64*ASTR],  Bl[64*ASTR];
    int tid = threadIdx.x, lane = tid & 31, wid = tid >> 5;
    int wm = wid >> 1, wn = wid & 1;
    int g = lane >> 2, c2 = (lane & 3)*2;
    int m0 = blockIdx.y*128, n0 = blockIdx.x*64;
    int slice = blockIdx.z;
    float acc[8][4] = {};
    for (int kc = 0; kc < 7*D_; kc += 32){
        int khw = slice*7 + kc/D_;
        int cib = kc % D_;
        int kh = khw/7, kw = khw%7;
        #pragma unroll
        for (int i = 0; i < 4; i++){
            int e = tid + i*256;
            int row = e >> 3, kg = (e & 7)*4;
            int m = m0 + row;
            uint2 h = make_uint2(0u,0u), l = h;
            if (m < MOUT){
                int bb = m / NOUT, rr = m % NOUT;
                int oh = rr / QG, ow = rr % QG;
                int ih = oh*3 - 3 + kh, iw = ow*3 - 3 + kw;
                if ((unsigned)ih < 64u && (unsigned)iw < 64u){
                    size_t off = ((size_t)(bb*NIN + ih*GW_ + iw))*D_ + cib + kg;
                    h = *(const uint2*)(Xh + off);
                    l = *(const uint2*)(Xl + off);
                }
            }
            *(uint2*)&Ah[row*ASTR + kg] = h;
            *(uint2*)&Al[row*ASTR + kg] = l;
        }
        fillB(Bh, Bl, Wh, Wl, (size_t)(khw*D_ + cib), CKK, n0, tid);
        __syncthreads();
        #pragma unroll
        for (int ks = 0; ks < 32; ks += 16){
            Frag f;
            load_frags(f, Ah, Al, Bh, Bl, wm, wn, ks, g, c2);
            do_mmas(acc, f);
        }
        __syncthreads();
    }
    epi(acc, (const float*)0, C, MOUT, D_, m0, n0, wm, wn, g, c2, 0, 1);
}

// ---------------- one-pass layernorm over D=384, optional residual-add -------------
__global__ void ln_kernel(const float* __restrict__ X, const float* __restrict__ g,
                          const float* __restrict__ bt, float* __restrict__ out, int add){
    int row = blockIdx.x, tid = threadIdx.x;
    float x = X[(size_t)row*D_ + tid];
    __shared__ float w1s[12], w2s[12];
    float s1 = x, s2 = x*x;
    #pragma unroll
    for (int o = 16; o > 0; o >>= 1){
        s1 += __shfl_down_sync(0xffffffffu, s1, o);
        s2 += __shfl_down_sync(0xffffffffu, s2, o);
    }
    if ((tid & 31) == 0){ w1s[tid >> 5] = s1; w2s[tid >> 5] = s2; }
    __syncthreads();
    if (tid == 0){
        float t1 = 0.f, t2 = 0.f;
        #pragma unroll
        for (int i = 0; i < 12; i++){ t1 += w1s[i]; t2 += w2s[i]; }
        w1s[0] = t1; w2s[0] = t2;
    }
    __syncthreads();
    float mu  = w1s[0] * (1.0f/D_);
    float var = w2s[0] * (1.0f/D_) - mu*mu;
    float y = (x - mu) * rsqrtf(var + LNEPS) * g[tid] + bt[tid];
    size_t o_ = (size_t)row*D_ + tid;
    out[o_] = add ? (out[o_] + y) : y;
}

// ======== HMMA scores (hi-only QK, k-tile 256): E = exp(Q K^T); d = E-1 fp16 ========
__global__ __launch_bounds__(256)
void mscore_kernel(const __nv_bfloat16* __restrict__ Qh,
                   const __nv_bfloat16* __restrict__ Kh,
                   __half* __restrict__ Eh, float* __restrict__ rowsum){
    __shared__ __align__(16) __nv_bfloat16 Qhs[64*ASTR];
    __shared__ __align__(16) __nv_bfloat16 Khs[256*ASTR];
    __shared__ float rs[64];
    int tid = threadIdx.x, lane = tid & 31, wid = tid >> 5;
    int wq = wid >> 2, wk = wid & 3;
    int g = lane >> 2, c2 = (lane & 3)*2;
    int kt = blockIdx.x*256, q0 = blockIdx.y*64, bh = blockIdx.z;
    if (tid < 64) rs[tid] = 0.f;
    {
        int row = tid >> 2, kb = (tid & 3)*8;
        unsigned* sh = (unsigned*)&Qhs[row*ASTR + kb];
        if (q0 + row < NOUT){
            size_t e32 = ((size_t)(bh*NOUT + q0 + row)*HD_ + kb) >> 1;
            const unsigned* ph = (const unsigned*)Qh + e32;
            #pragma unroll
            for (int j = 0; j < 4; j++) sh[j] = ph[j];
        } else {
            #pragma unroll
            for (int j = 0; j < 4; j++) sh[j] = 0u;
        }
    }
    {
        int row = tid;   // 256 rows, 32 halfs each
        size_t e32 = ((size_t)(bh*NIN + kt + row)*HD_) >> 1;
        const unsigned* ph = (const unsigned*)Kh + e32;
        unsigned* sh = (unsigned*)&Khs[row*ASTR];
        #pragma unroll
        for (int j = 0; j < 16; j++) sh[j] = ph[j];
    }
    __syncthreads();
    #pragma unroll
    for (int khalf = 0; khalf < 2; khalf++){
        float acc[2][4][4] = {};
        #pragma unroll
        for (int ks = 0; ks < 32; ks += 16){
            unsigned ah[2][4], bhf[4][2];
            #pragma unroll
            for (int t = 0; t < 2; t++){
                int rb = (wq*32 + t*16 + g)*ASTR + ks + c2;
                ah[t][0] = *(const unsigned*)(Qhs + rb);
                ah[t][1] = *(const unsigned*)(Qhs + rb + 8*ASTR);
                ah[t][2] = *(const unsigned*)(Qhs + rb + 8);
                ah[t][3] = *(const unsigned*)(Qhs + rb + 8*ASTR + 8);
            }
            #pragma unroll
            for (int u = 0; u < 4; u++){
                int nb = (khalf*128 + wk*32 + u*8 + g)*ASTR + ks + c2;
                bhf[u][0] = *(const unsigned*)(Khs + nb);
                bhf[u][1] = *(const unsigned*)(Khs + nb + 8);
            }
            #pragma unroll
            for (int t = 0; t < 2; t++)
                #pragma unroll
                for (int u = 0; u < 4; u++)
                    mma16816(acc[t][u], ah[t], bhf[u]);
        }
        #pragma unroll
        for (int t = 0; t < 2; t++){
            int lr = wq*32 + t*16 + g;
            int r  = q0 + lr;
            float s0 = 0.f, s1 = 0.f;
            #pragma unroll
            for (int u = 0; u < 4; u++){
                int col = kt + khalf*128 + wk*32 + u*8 + c2;
                float e0 = exp_fast(acc[t][u][0]), e1 = exp_fast(acc[t][u][1]);
                float e2 = exp_fast(acc[t][u][2]), e3 = exp_fast(acc[t][u][3]);
                __half2 v0 = __floats2half2_rn(e0 - 1.0f, e1 - 1.0f);
                __half2 v1 = __floats2half2_rn(e2 - 1.0f, e3 - 1.0f);
                if (r < NOUT)
                    *(__half2*)(Eh + (size_t)(bh*NOUT + r)*NIN + col) = v0;
                if (r + 8 < NOUT)
                    *(__half2*)(Eh + (size_t)(bh*NOUT + r + 8)*NIN + col) = v1;
                s0 += e0 + e1; s1 += e2 + e3;
            }
            s0 += __shfl_xor_sync(0xffffffffu, s0, 1);
            s0 += __shfl_xor_sync(0xffffffffu, s0, 2);
            s1 += __shfl_xor_sync(0xffffffffu, s1, 1);
            s1 += __shfl_xor_sync(0xffffffffu, s1, 2);
            if ((lane & 3) == 0){
                atomicAdd(&rs[lr], s0);
                atomicAdd(&rs[lr + 8], s1);
            }
        }
    }
    __syncthreads();
    if (tid < 64 && q0 + tid < NOUT)
        atomicAdd(rowsum + bh*NOUT + q0 + tid, rs[tid]);
}

// colsum with fused row-reciprocal (rowsum is raw sums)
__global__ void colsum_kernel(const __half* __restrict__ Eh, const float* __restrict__ rowsum,
                              float* __restrict__ colinv){
    __shared__ float ris[NOUT];
    int bh = blockIdx.y;
    int tid = threadIdx.x;
    for (int i = tid; i < NOUT; i += 256)
        ris[i] = 1.f / rowsum[bh*NOUT + i];
    __syncthreads();
    int col = blockIdx.x*256 + tid;
    const __half* a = Eh + (size_t)bh*NOUT*NIN + col;
    float s = 0.f;
    #pragma unroll 4
    for (int qi = 0; qi < NOUT; qi++)
        s += (1.0f + __half2float(a[(size_t)qi*NIN])) * ris[qi];
    colinv[bh*NIN + col] = 1.f / (s + EPSV);
}

// ======== HMMA PV: upd += (E*rinv*colinv) @ V, split-K=4, atomic epilogue ========
// rowsum raw; reciprocals computed inline.
#define PSTR 72
__global__ __launch_bounds__(256)
void mpv_kernel(const __half* __restrict__ Eh,
                const float* __restrict__ rowsum, const float* __restrict__ colinv,
                const __nv_bfloat16* __restrict__ Vth, const __nv_bfloat16* __restrict__ Vtl,
                float* __restrict__ out, float* __restrict__ outk, float* __restrict__ outq,
                int writeout){
    __shared__ __align__(16) __nv_bfloat16 Ahs[64*PSTR], Als[64*PSTR];
    __shared__ __align__(16) __nv_bfloat16 Vhs[32*PSTR], Vls[32*PSTR];
    int tid = threadIdx.x, lane = tid & 31, wid = tid >> 5;
    int wq = wid >> 1, wd = wid & 1;
    int g = lane >> 2, c2 = (lane & 3)*2;
    int q0 = blockIdx.x*64, bh = blockIdx.y;
    int ks0 = blockIdx.z*1024;
    float acc[2][4] = {};
    int frow = tid >> 4, fcol = (tid & 15)*4;
    float rv[4];
    #pragma unroll
    for (int i = 0; i < 4; i++){
        int r = q0 + frow + i*16;
        rv[i] = (r < NOUT) ? 1.f / rowsum[bh*NOUT + r] : 0.f;
    }
    for (int c = 0; c < 16; c++){
        int k0 = ks0 + c*64;
        #pragma unroll
        for (int i = 0; i < 4; i++){
            int row = frow + i*16;
            int r = q0 + row;
            float4 e = make_float4(0.f,0.f,0.f,0.f);
            size_t base = (size_t)(bh*NOUT + (r < NOUT ? r : 0))*NIN + k0 + fcol;
            if (r < NOUT){
                uint2 u = *(const uint2*)(Eh + base);
                float2 f0 = __half22float2(*(__half2*)&u.x);
                float2 f1 = __half22float2(*(__half2*)&u.y);
                e = make_float4(1.0f + f0.x, 1.0f + f0.y, 1.0f + f1.x, 1.0f + f1.y);
            }
            float4 cv = *(const float4*)(colinv + bh*NIN + k0 + fcol);
            float4 a;
            a.x = e.x*rv[i]*cv.x; a.y = e.y*rv[i]*cv.y;
            a.z = e.z*rv[i]*cv.z; a.w = e.w*rv[i]*cv.w;
            if (writeout && r < NOUT){
                float4 ak;
                ak.x = e.x*rv[i]; ak.y = e.y*rv[i];
                ak.z = e.z*rv[i]; ak.w = e.w*rv[i];
                *(float4*)(outk + base) = ak;
                *(float4*)(outq + base) = a;
            }
            unsigned h0,h1,l0,l1; split4(a, h0,h1,l0,l1);
            unsigned* ph = (unsigned*)&Ahs[row*PSTR + fcol];
            unsigned* pl = (unsigned*)&Als[row*PSTR + fcol];
            ph[0]=h0; ph[1]=h1; pl[0]=l0; pl[1]=l1;
        }
        {
            int d = tid >> 3, kb = (tid & 7)*8;
            size_t e32 = ((size_t)(bh*HD_ + d)*NIN + k0 + kb) >> 1;
            const unsigned* ph = (const unsigned*)Vth + e32;
            const unsigned* pl = (const unsigned*)Vtl + e32;
            unsigned* sh = (unsigned*)&Vhs[d*PSTR + kb];
            unsigned* sl = (unsigned*)&Vls[d*PSTR + kb];
            #pragma unroll
            for (int j = 0; j < 4; j++){ sh[j] = ph[j]; sl[j] = pl[j]; }
        }
        __syncthreads();
        #pragma unroll
        for (int ks = 0; ks < 64; ks += 16){
            unsigned a_h[4], a_l[4];
            int rb = (wq*16 + g)*PSTR + ks + c2;
            a_h[0] = *(const unsigned*)(Ahs + rb);
            a_h[1] = *(const unsigned*)(Ahs + rb + 8*PSTR);
            a_h[2] = *(const unsigned*)(Ahs + rb + 8);
            a_h[3] = *(const unsigned*)(Ahs + rb + 8*PSTR + 8);
            a_l[0] = *(const unsigned*)(Als + rb);
            a_l[1] = *(const unsigned*)(Als + rb + 8*PSTR);
            a_l[2] = *(const unsigned*)(Als + rb + 8);
            a_l[3] = *(const unsigned*)(Als + rb + 8*PSTR + 8);
            #pragma unroll
            for (int u = 0; u < 2; u++){
                unsigned b_h[2], b_l[2];
                int nb = (wd*16 + u*8 + g)*PSTR + ks + c2;
                b_h[0] = *(const unsigned*)(Vhs + nb);
                b_h[1] = *(const unsigned*)(Vhs + nb + 8);
                b_l[0] = *(const unsigned*)(Vls + nb);
                b_l[1] = *(const unsigned*)(Vls + nb + 8);
                mma16816(acc[u], a_h, b_h);
                mma16816(acc[u], a_h, b_l);
                mma16816(acc[u], a_l, b_h);
            }
        }
        __syncthreads();
    }
    int b = bh / H_, h = bh % H_;
    int r0 = q0 + wq*16 + g;
    #pragma unroll
    for (int u = 0; u < 2; u++){
        int col = h*HD_ + wd*16 + u*8 + c2;
        if (r0 < NOUT){
            atomicAdd(out + (size_t)(b*NOUT + r0)*D_ + col,     acc[u][0]);
            atomicAdd(out + (size_t)(b*NOUT + r0)*D_ + col + 1, acc[u][1]);
        }
        if (r0 + 8 < NOUT){
            atomicAdd(out + (size_t)(b*NOUT + r0 + 8)*D_ + col,     acc[u][2]);
            atomicAdd(out + (size_t)(b*NOUT + r0 + 8)*D_ + col + 1, acc[u][3]);
        }
    }
}

// ---------------- host orchestration ----------------------------------------------
extern "C" void kernel_launch(void* const* d_in, const int* in_sizes, int n_in,
                              void* d_out, int out_size){
    const float* x      = (const float*)d_in[0];
    const float* conv_w = (const float*)d_in[1];
    const float* conv_b = (const float*)d_in[2];
    const float* kv_w   = (const float*)d_in[3];
    const float* kv_b   = (const float*)d_in[4];
    const float* q_w    = (const float*)d_in[5];
    const float* q_b    = (const float*)d_in[6];
    const float* w1     = (const float*)d_in[7];
    const float* b1m    = (const float*)d_in[8];
    const float* w2     = (const float*)d_in[9];
    const float* b2m    = (const float*)d_in[10];
    const float* g1     = (const float*)d_in[11];
    const float* b1_    = (const float*)d_in[12];
    const float* g2     = (const float*)d_in[13];
    const float* b2_    = (const float*)d_in[14];
    const float* g3     = (const float*)d_in[15];
    const float* b3_    = (const float*)d_in[16];
    const float* temp   = (const float*)d_in[17];
    const float* freqs  = (const float*)d_in[18];

    __nv_bfloat16 *cwh,*cwl,*kvwh,*kvwl,*qwh,*qwl,*w1h,*w1l,*w2h,*w2l;
    __nv_bfloat16 *xh,*xl,*kh,*kl,*vth,*vtl,*qh,*ql;
    float *xo,*xoutg,*kv,*qlin,*attn_s,*rowsum,*colinv,*h1;
    cudaGetSymbolAddress((void**)&cwh,  g_cwh);  cudaGetSymbolAddress((void**)&cwl,  g_cwl);
    cudaGetSymbolAddress((void**)&kvwh, g_kvwh); cudaGetSymbolAddress((void**)&kvwl, g_kvwl);
    cudaGetSymbolAddress((void**)&qwh,  g_qwh);  cudaGetSymbolAddress((void**)&qwl,  g_qwl);
    cudaGetSymbolAddress((void**)&w1h,  g_w1h);  cudaGetSymbolAddress((void**)&w1l,  g_w1l);
    cudaGetSymbolAddress((void**)&w2h,  g_w2h);  cudaGetSymbolAddress((void**)&w2l,  g_w2l);
    cudaGetSymbolAddress((void**)&xh,   g_xh);   cudaGetSymbolAddress((void**)&xl,   g_xl);
    cudaGetSymbolAddress((void**)&kh,   g_kh);   cudaGetSymbolAddress((void**)&kl,   g_kl);
    cudaGetSymbolAddress((void**)&vth,  g_vth);  cudaGetSymbolAddress((void**)&vtl,  g_vtl);
    cudaGetSymbolAddress((void**)&qh,   g_qh);   cudaGetSymbolAddress((void**)&ql,   g_ql);
    cudaGetSymbolAddress((void**)&xo,     g_xo);
    cudaGetSymbolAddress((void**)&xoutg,  g_xout);
    cudaGetSymbolAddress((void**)&kv,     g_kv);
    cudaGetSymbolAddress((void**)&qlin,   g_qlin);
    cudaGetSymbolAddress((void**)&attn_s, g_attn);
    cudaGetSymbolAddress((void**)&rowsum, g_rowsum);
    cudaGetSymbolAddress((void**)&colinv, g_colinv);
    cudaGetSymbolAddress((void**)&h1,     g_h1);

    float* out = (float*)d_out;
    bool full = (size_t)out_size >= (size_t)XOUT_SZ + 2*ATTN_SZ;
    float* xout      = full ? out : xoutg;                       // x_out in place
    float* out_attnq = full ? out + XOUT_SZ : attn_s;
    float* out_attnk = full ? out + XOUT_SZ + ATTN_SZ : attn_s;
    __half* Eh       = (__half*)attn_s;                          // fp16 (E-1), all iters

    // ---- prologue: pack weights + pre-split x ----
    packconvT_kernel<<<D_, 256>>>(conv_w, cwh, cwl);
    packT_kernel<<<(D_*2*D_ + 255)/256, 256>>>(kv_w, kvwh, kvwl, D_, 2*D_);
    packT_kernel<<<(D_*D_ + 255)/256, 256>>>(q_w, qwh, qwl, D_, D_);
    packT_kernel<<<(D_*4*D_ + 255)/256, 256>>>(w1, w1h, w1l, D_, 4*D_);
    packT_kernel<<<(4*D_*D_ + 255)/256, 256>>>(w2, w2h, w2l, 4*D_, D_);
    splitf_kernel<<<(MIN_*D_ + 255)/256, 256>>>(x, xh, xl, MIN_*D_);

    // ---- conv + first LN ----
    seed_kernel<<<(MOUT*D_ + 255)/256, 256>>>(conv_b, xo, MOUT, D_);
    mconv_kernel<<<dim3(D_/64, (MOUT+127)/128, 7), 256>>>(xh, xl, cwh, cwl, xo);
    ln_kernel<<<MOUT, D_>>>(xo, g1, b1_, xout, 0);

    // ---- kv (loop-invariant) + rose-split ----
    mgemm_pre_kernel<<<dim3(2*D_/64, MIN_/128), 256>>>(xh, xl, kvwh, kvwl, kv_b, kv, MIN_, 2*D_, D_);
    int totk = BH_*NIN*HD_;
    rose_hl_kernel<<<(totk+255)/256, 256>>>(kv, 2*D_, 0, kh, kl, NIN, GW_, 1.f, 1.f, freqs, temp, 1);
    vT_hl_kernel<<<(totk+255)/256, 256>>>(kv, vth, vtl);

    int totq = BH_*NOUT*HD_;
    for (int it = 0; it < 3; it++){
        int writeout = (it == 2 && full) ? 1 : 0;
        prep_kernel<<<(MOUT*D_ + 255)/256, 256>>>(q_b, qlin, xo, rowsum);
        mgemm_kernel<<<dim3(D_/64, (MOUT+127)/128, 4), 256>>>(xout, qwh, qwl, q_b, qlin, MOUT, D_, D_, D_/4, 0, 1);
        rose_hl_kernel<<<(totq+255)/256, 256>>>(qlin, D_, 0, qh, ql, NOUT, QG, 3.f, 3.f, freqs, temp, 0);

        mscore_kernel<<<dim3(NIN/256, (NOUT+63)/64, BH_), 256>>>(qh, kh, Eh, rowsum);
        colsum_kernel<<<dim3(NIN/256, BH_), 256>>>(Eh, rowsum, colinv);
        mpv_kernel<<<dim3((NOUT+63)/64, BH_, 4), 256>>>(Eh, rowsum, colinv, vth, vtl,
                                                        xo, out_attnk, out_attnq, writeout);
        ln_kernel<<<MOUT, D_>>>(xo, g2, b2_, xout, 1);

        mgemm_kernel<<<dim3(4*D_/64, (MOUT+127)/128, 1), 256>>>(xout, w1h, w1l, b1m, h1, MOUT, 4*D_, D_, D_, 1, 0);
        seed_kernel<<<(MOUT*D_ + 255)/256, 256>>>(b2m, xo, MOUT, D_);
        mgemm_kernel<<<dim3(D_/64, (MOUT+127)/128, 4), 256>>>(h1, w2h, w2l, b2m, xo, MOUT, D_, 4*D_, D_, 0, 1);
        ln_kernel<<<MOUT, D_>>>(xo, g3, b3_, xout, 1);
    }
}